// round 3
// baseline (speedup 1.0000x reference)
#include <cuda_runtime.h>
#include <cstddef>

#define BB 1024   // batch
#define TT 512    // time steps
#define II 64     // input dim
#define HH 256    // hidden dim
#define G4 1024   // 4*H
#define NBLK 128  // persistent CTAs (tiles per phase per layer)

// ---------------- persistent device scratch ----------------
__device__ float g_W0[G4 * (II + HH)];   // [4H, 320] packed [w_ih0 | w_hh0]
__device__ float g_W1[G4 * (HH + HH)];   // [4H, 512] packed [w_ih1 | w_hh1]
__device__ float g_b0[G4];
__device__ float g_b1[G4];
__device__ float g_h0[2][BB * HH];       // ping-pong hidden, layer 0
__device__ float g_h1[2][BB * HH];       // ping-pong hidden, layer 1
__device__ float g_c0[BB * HH];
__device__ float g_c1[BB * HH];
__device__ unsigned g_bar_count;
__device__ unsigned g_bar_gen;

// ---------------- weight packing + state init ----------------
__global__ void pack_init(const float* __restrict__ w_ih0, const float* __restrict__ w_hh0,
                          const float* __restrict__ b_ih0, const float* __restrict__ b_hh0,
                          const float* __restrict__ w_ih1, const float* __restrict__ w_hh1,
                          const float* __restrict__ b_ih1, const float* __restrict__ b_hh1)
{
    const int tid = blockIdx.x * blockDim.x + threadIdx.x;
    const int stride = gridDim.x * blockDim.x;

    const int KC0 = II + HH;   // 320
    const int KC1 = HH + HH;   // 512

    for (int idx = tid; idx < G4 * KC0; idx += stride) {
        int n = idx / KC0, k = idx - n * KC0;
        g_W0[idx] = (k < II) ? w_ih0[n * II + k] : w_hh0[n * HH + (k - II)];
    }
    for (int idx = tid; idx < G4 * KC1; idx += stride) {
        int n = idx / KC1, k = idx - n * KC1;
        g_W1[idx] = (k < HH) ? w_ih1[n * HH + k] : w_hh1[n * HH + (k - HH)];
    }
    for (int idx = tid; idx < G4; idx += stride) {
        g_b0[idx] = b_ih0[idx] + b_hh0[idx];
        g_b1[idx] = b_ih1[idx] + b_hh1[idx];
    }
    for (int idx = tid; idx < BB * HH; idx += stride) {
        g_h0[0][idx] = 0.f;
        g_h1[0][idx] = 0.f;
        g_c0[idx] = 0.f;
        g_c1[idx] = 0.f;
    }
    if (tid == 0) { g_bar_count = 0; g_bar_gen = 0; }
}

// ---------------- grid-wide barrier ----------------
__device__ __forceinline__ void grid_sync()
{
    __threadfence();            // publish this CTA's writes
    __syncthreads();
    if (threadIdx.x == 0) {
        unsigned gen = *(volatile unsigned*)&g_bar_gen;
        if (atomicAdd(&g_bar_count, 1u) == (unsigned)(NBLK - 1)) {
            *(volatile unsigned*)&g_bar_count = 0u;
            __threadfence();
            *(volatile unsigned*)&g_bar_gen = gen + 1u;
        } else {
            while (*(volatile unsigned*)&g_bar_gen == gen) { __nanosleep(64); }
        }
    }
    __syncthreads();
}

// ---------------- one [64 x 32] LSTM tile (GEMM + cell) ----------------
// As: [32][68] (k-major, padded), Ws: [32][128] (k-major, gate*32+n_local)
template <int KIN>
__device__ __forceinline__ void lstm_tile(
    const float* __restrict__ xin, int xstride,
    const float* __restrict__ hprev,
    const float* __restrict__ Wc, const float* __restrict__ bias,
    float* __restrict__ c, float* __restrict__ hout,
    float (*As)[68], float (*Ws)[128],
    int m0, int n0)
{
    constexpr int KC = KIN + HH;
    constexpr int BK = 32;

    const int tid = threadIdx.x;
    const int tx = tid & 31;
    const int ty = tid >> 5;

    float acc[4][8];
#pragma unroll
    for (int g = 0; g < 4; ++g)
#pragma unroll
        for (int r = 0; r < 8; ++r) acc[g][r] = 0.f;

    const int aM = tid >> 2;           // 0..63
    const int aK = (tid & 3) * 8;      // 0,8,16,24
    const int wR = tid >> 1;           // 0..127
    const int wK = (tid & 1) * 16;     // 0 or 16
    const int wGate = wR >> 5;
    const int wRowG = wGate * HH + n0 + (wR & 31);
    const float* wptr = Wc + (size_t)wRowG * KC;

    for (int k0 = 0; k0 < KC; k0 += BK) {
        {
            const int mg = m0 + aM;
#pragma unroll
            for (int j = 0; j < 8; ++j) {
                const int gk = k0 + aK + j;
                float v;
                if (gk < KIN) v = xin[(size_t)mg * xstride + gk];
                else          v = hprev[mg * HH + (gk - KIN)];
                As[aK + j][aM] = v;
            }
        }
        {
            const float4* p = (const float4*)(wptr + k0 + wK);
#pragma unroll
            for (int j = 0; j < 4; ++j) {
                float4 v = p[j];
                Ws[wK + j * 4 + 0][wR] = v.x;
                Ws[wK + j * 4 + 1][wR] = v.y;
                Ws[wK + j * 4 + 2][wR] = v.z;
                Ws[wK + j * 4 + 3][wR] = v.w;
            }
        }
        __syncthreads();

#pragma unroll
        for (int kk = 0; kk < BK; ++kk) {
            float4 a0 = *(const float4*)&As[kk][ty * 8];
            float4 a1 = *(const float4*)&As[kk][ty * 8 + 4];
            float a[8] = {a0.x, a0.y, a0.z, a0.w, a1.x, a1.y, a1.z, a1.w};
            const float wi = Ws[kk][tx];
            const float wf = Ws[kk][32 + tx];
            const float wg = Ws[kk][64 + tx];
            const float wo = Ws[kk][96 + tx];
#pragma unroll
            for (int r = 0; r < 8; ++r) {
                acc[0][r] = fmaf(a[r], wi, acc[0][r]);
                acc[1][r] = fmaf(a[r], wf, acc[1][r]);
                acc[2][r] = fmaf(a[r], wg, acc[2][r]);
                acc[3][r] = fmaf(a[r], wo, acc[3][r]);
            }
        }
        __syncthreads();
    }

    const int n = n0 + tx;
    const float bi = bias[n];
    const float bf = bias[HH + n];
    const float bg = bias[2 * HH + n];
    const float bo = bias[3 * HH + n];
#pragma unroll
    for (int r = 0; r < 8; ++r) {
        const int m = m0 + ty * 8 + r;
        const float ig = 1.f / (1.f + __expf(-(acc[0][r] + bi)));
        const float fg = 1.f / (1.f + __expf(-(acc[1][r] + bf)));
        const float gx = acc[2][r] + bg;
        const float gg = 2.f / (1.f + __expf(-2.f * gx)) - 1.f;   // tanh
        const float og = 1.f / (1.f + __expf(-(acc[3][r] + bo)));
        const float cold = c[m * HH + n];
        const float cn = fg * cold + ig * gg;
        c[m * HH + n] = cn;
        const float th = 2.f / (1.f + __expf(-2.f * cn)) - 1.f;   // tanh(cn)
        hout[m * HH + n] = og * th;
    }
}

// ---------------- persistent fused LSTM (both layers, all timesteps) ----------------
// Phase p: layer0 at t=p (p<TT) and layer1 at t=p-1 (p>0), then grid barrier.
// Buffer convention: h(t) lives in buf[(t+1)&1]; h(-1)=zeros in buf[0].
__global__ __launch_bounds__(256, 1) void lstm_persistent(const float* __restrict__ x)
{
    __shared__ __align__(16) float As[32][68];
    __shared__ __align__(16) float Ws[32][128];

    const int b = blockIdx.x;          // 0..127
    const int m0 = (b & 15) * 64;
    const int n0 = (b >> 4) * 32;

    float* h0[2] = { g_h0[0], g_h0[1] };
    float* h1[2] = { g_h1[0], g_h1[1] };

    for (int p = 0; p <= TT; ++p) {
        if (p < TT) {
            // layer0, t = p: reads x(t), h0 buf[p&1]; writes h0 buf[(p+1)&1]
            lstm_tile<II>(x + (size_t)p * II, TT * II,
                          h0[p & 1], g_W0, g_b0, g_c0, h0[(p + 1) & 1],
                          As, Ws, m0, n0);
        }
        if (p > 0) {
            // layer1, t = p-1: reads h0 buf[p&1], h1 buf[(p-1)&1]; writes h1 buf[p&1]
            lstm_tile<HH>(h0[p & 1], HH,
                          h1[(p - 1) & 1], g_W1, g_b1, g_c1, h1[p & 1],
                          As, Ws, m0, n0);
        }
        grid_sync();
    }
}

// ---------------- final FC (O=1) ----------------
__global__ void fc_kernel(const float* __restrict__ fc_w, const float* __restrict__ fc_b,
                          float* __restrict__ out)
{
    // h1(T-1) lives in buf[((T-1)+1)&1] = buf[0]
    const float* h = g_h1[TT & 1];
    const int warp = (blockIdx.x * blockDim.x + threadIdx.x) >> 5;
    const int lane = threadIdx.x & 31;
    if (warp >= BB) return;
    float s = 0.f;
    for (int k = lane; k < HH; k += 32) s += h[warp * HH + k] * fc_w[k];
#pragma unroll
    for (int off = 16; off; off >>= 1) s += __shfl_xor_sync(0xffffffffu, s, off);
    if (lane == 0) out[warp] = s + fc_b[0];
}

// ---------------- launch ----------------
extern "C" void kernel_launch(void* const* d_in, const int* in_sizes, int n_in,
                              void* d_out, int out_size)
{
    const float* x     = (const float*)d_in[0];
    const float* w_ih0 = (const float*)d_in[1];
    const float* w_hh0 = (const float*)d_in[2];
    const float* b_ih0 = (const float*)d_in[3];
    const float* b_hh0 = (const float*)d_in[4];
    const float* w_ih1 = (const float*)d_in[5];
    const float* w_hh1 = (const float*)d_in[6];
    const float* b_ih1 = (const float*)d_in[7];
    const float* b_hh1 = (const float*)d_in[8];
    const float* fc_w  = (const float*)d_in[9];
    const float* fc_b  = (const float*)d_in[10];
    float* out = (float*)d_out;

    pack_init<<<512, 256>>>(w_ih0, w_hh0, b_ih0, b_hh0, w_ih1, w_hh1, b_ih1, b_hh1);
    lstm_persistent<<<NBLK, 256>>>(x);
    fc_kernel<<<BB * 32 / 256, 256>>>(fc_w, fc_b, out);
}

// round 4
// speedup vs baseline: 1.0736x; 1.0736x over previous
#include <cuda_runtime.h>
#include <cstddef>

#define BB 1024   // batch
#define TT 512    // time steps
#define II 64     // input dim
#define HH 256    // hidden dim
#define G4 1024   // 4*H
#define NBLK 128  // persistent CTAs (tiles per phase per layer)

// ---------------- persistent device scratch ----------------
__device__ float g_W0[G4 * (II + HH)];   // [4H, 320] packed [w_ih0 | w_hh0]
__device__ float g_W1[G4 * (HH + HH)];   // [4H, 512] packed [w_ih1 | w_hh1]
__device__ float g_b0[G4];
__device__ float g_b1[G4];
__device__ float g_h0[2][BB * HH];       // ping-pong hidden, layer 0
__device__ float g_h1[2][BB * HH];       // ping-pong hidden, layer 1
__device__ float g_c0[BB * HH];
__device__ float g_c1[BB * HH];
__device__ unsigned g_bar_count;
__device__ unsigned g_bar_gen;

// ---------------- packed f32x2 helpers ----------------
__device__ __forceinline__ unsigned long long pack2(float w)
{
    unsigned long long r;
    asm("mov.b64 %0, {%1, %1};" : "=l"(r) : "f"(w));
    return r;
}
__device__ __forceinline__ void ffma2(unsigned long long& d,
                                      unsigned long long a,
                                      unsigned long long b)
{
    asm("fma.rn.f32x2 %0, %1, %2, %0;" : "+l"(d) : "l"(a), "l"(b));
}
__device__ __forceinline__ void unpack2(unsigned long long v, float& lo, float& hi)
{
    asm("mov.b64 {%0, %1}, %2;" : "=f"(lo), "=f"(hi) : "l"(v));
}

// ---------------- weight packing + state init ----------------
__global__ void pack_init(const float* __restrict__ w_ih0, const float* __restrict__ w_hh0,
                          const float* __restrict__ b_ih0, const float* __restrict__ b_hh0,
                          const float* __restrict__ w_ih1, const float* __restrict__ w_hh1,
                          const float* __restrict__ b_ih1, const float* __restrict__ b_hh1)
{
    const int tid = blockIdx.x * blockDim.x + threadIdx.x;
    const int stride = gridDim.x * blockDim.x;

    const int KC0 = II + HH;   // 320
    const int KC1 = HH + HH;   // 512

    for (int idx = tid; idx < G4 * KC0; idx += stride) {
        int n = idx / KC0, k = idx - n * KC0;
        g_W0[idx] = (k < II) ? w_ih0[n * II + k] : w_hh0[n * HH + (k - II)];
    }
    for (int idx = tid; idx < G4 * KC1; idx += stride) {
        int n = idx / KC1, k = idx - n * KC1;
        g_W1[idx] = (k < HH) ? w_ih1[n * HH + k] : w_hh1[n * HH + (k - HH)];
    }
    for (int idx = tid; idx < G4; idx += stride) {
        g_b0[idx] = b_ih0[idx] + b_hh0[idx];
        g_b1[idx] = b_ih1[idx] + b_hh1[idx];
    }
    for (int idx = tid; idx < BB * HH; idx += stride) {
        g_h0[0][idx] = 0.f;
        g_h1[0][idx] = 0.f;
        g_c0[idx] = 0.f;
        g_c1[idx] = 0.f;
    }
    if (tid == 0) { g_bar_count = 0; g_bar_gen = 0; }
}

// ---------------- grid-wide barrier ----------------
__device__ __forceinline__ void grid_sync()
{
    __threadfence();            // publish this CTA's writes
    __syncthreads();
    if (threadIdx.x == 0) {
        unsigned gen = *(volatile unsigned*)&g_bar_gen;
        if (atomicAdd(&g_bar_count, 1u) == (unsigned)(NBLK - 1)) {
            *(volatile unsigned*)&g_bar_count = 0u;
            __threadfence();
            *(volatile unsigned*)&g_bar_gen = gen + 1u;
        } else {
            while (*(volatile unsigned*)&g_bar_gen == gen) { __nanosleep(64); }
        }
    }
    __syncthreads();
}

// ---------------- one [64 x 32] LSTM tile (GEMM + cell, f32x2 packed) ----------------
// As: [32][68] (k-major, padded), Ws: [32][128] (k-major, gate*32+n_local)
template <int KIN>
__device__ __forceinline__ void lstm_tile(
    const float* __restrict__ xin, int xstride,
    const float* __restrict__ hprev,
    const float* __restrict__ Wc, const float* __restrict__ bias,
    float* __restrict__ c, float* __restrict__ hout,
    float (*As)[68], float (*Ws)[128],
    int m0, int n0)
{
    constexpr int KC = KIN + HH;
    constexpr int BK = 32;

    const int tid = threadIdx.x;
    const int tx = tid & 31;
    const int ty = tid >> 5;

    // 4 gates x 4 row-pairs, each pair = packed f32x2 (rows 2p, 2p+1)
    unsigned long long acc2[4][4];
#pragma unroll
    for (int g = 0; g < 4; ++g)
#pragma unroll
        for (int p = 0; p < 4; ++p) acc2[g][p] = 0ull;

    const int aM = tid >> 2;           // 0..63
    const int aK = (tid & 3) * 8;      // 0,8,16,24
    const int wR = tid >> 1;           // 0..127
    const int wK = (tid & 1) * 16;     // 0 or 16
    const int wGate = wR >> 5;
    const int wRowG = wGate * HH + n0 + (wR & 31);
    const float* wptr = Wc + (size_t)wRowG * KC;

    for (int k0 = 0; k0 < KC; k0 += BK) {
        // ---- load A chunk: [x_t | h_prev] ----
        {
            const int mg = m0 + aM;
#pragma unroll
            for (int j = 0; j < 8; ++j) {
                const int gk = k0 + aK + j;
                float v;
                if (gk < KIN) v = xin[(size_t)mg * xstride + gk];
                else          v = hprev[mg * HH + (gk - KIN)];
                As[aK + j][aM] = v;
            }
        }
        // ---- load W chunk (16 consecutive k as 4x float4) ----
        {
            const float4* p = (const float4*)(wptr + k0 + wK);
#pragma unroll
            for (int j = 0; j < 4; ++j) {
                float4 v = p[j];
                Ws[wK + j * 4 + 0][wR] = v.x;
                Ws[wK + j * 4 + 1][wR] = v.y;
                Ws[wK + j * 4 + 2][wR] = v.z;
                Ws[wK + j * 4 + 3][wR] = v.w;
            }
        }
        __syncthreads();

#pragma unroll
        for (int kk = 0; kk < BK; ++kk) {
            // 8 batch rows = 4 packed f32x2 pairs (rows adjacent in As)
            const ulonglong2 a01 = *(const ulonglong2*)&As[kk][ty * 8];
            const ulonglong2 a23 = *(const ulonglong2*)&As[kk][ty * 8 + 4];
            unsigned long long ap[4] = { a01.x, a01.y, a23.x, a23.y };
            const unsigned long long wi2 = pack2(Ws[kk][tx]);
            const unsigned long long wf2 = pack2(Ws[kk][32 + tx]);
            const unsigned long long wg2 = pack2(Ws[kk][64 + tx]);
            const unsigned long long wo2 = pack2(Ws[kk][96 + tx]);
#pragma unroll
            for (int p = 0; p < 4; ++p) {
                ffma2(acc2[0][p], ap[p], wi2);
                ffma2(acc2[1][p], ap[p], wf2);
                ffma2(acc2[2][p], ap[p], wg2);
                ffma2(acc2[3][p], ap[p], wo2);
            }
        }
        __syncthreads();
    }

    // ---- LSTM cell epilogue ----
    const int n = n0 + tx;
    const float bi = bias[n];
    const float bf = bias[HH + n];
    const float bg = bias[2 * HH + n];
    const float bo = bias[3 * HH + n];
#pragma unroll
    for (int p = 0; p < 4; ++p) {
        float ai[2], af[2], ag[2], ao[2];
        unpack2(acc2[0][p], ai[0], ai[1]);
        unpack2(acc2[1][p], af[0], af[1]);
        unpack2(acc2[2][p], ag[0], ag[1]);
        unpack2(acc2[3][p], ao[0], ao[1]);
#pragma unroll
        for (int q = 0; q < 2; ++q) {
            const int m = m0 + ty * 8 + p * 2 + q;
            const float ig = 1.f / (1.f + __expf(-(ai[q] + bi)));
            const float fg = 1.f / (1.f + __expf(-(af[q] + bf)));
            const float gx = ag[q] + bg;
            const float gg = 2.f / (1.f + __expf(-2.f * gx)) - 1.f;   // tanh
            const float og = 1.f / (1.f + __expf(-(ao[q] + bo)));
            const float cold = c[m * HH + n];
            const float cn = fg * cold + ig * gg;
            c[m * HH + n] = cn;
            const float th = 2.f / (1.f + __expf(-2.f * cn)) - 1.f;   // tanh(cn)
            hout[m * HH + n] = og * th;
        }
    }
}

// ---------------- persistent fused LSTM (both layers, all timesteps) ----------------
// Phase p: layer0 at t=p (p<TT) and layer1 at t=p-1 (p>0), then grid barrier.
// Buffer convention: h(t) lives in buf[(t+1)&1]; h(-1)=zeros in buf[0].
__global__ __launch_bounds__(256, 1) void lstm_persistent(const float* __restrict__ x)
{
    __shared__ __align__(16) float As[32][68];
    __shared__ __align__(16) float Ws[32][128];

    const int b = blockIdx.x;          // 0..127
    const int m0 = (b & 15) * 64;
    const int n0 = (b >> 4) * 32;

    float* h0[2] = { g_h0[0], g_h0[1] };
    float* h1[2] = { g_h1[0], g_h1[1] };

    for (int p = 0; p <= TT; ++p) {
        if (p < TT) {
            lstm_tile<II>(x + (size_t)p * II, TT * II,
                          h0[p & 1], g_W0, g_b0, g_c0, h0[(p + 1) & 1],
                          As, Ws, m0, n0);
        }
        if (p > 0) {
            lstm_tile<HH>(h0[p & 1], HH,
                          h1[(p - 1) & 1], g_W1, g_b1, g_c1, h1[p & 1],
                          As, Ws, m0, n0);
        }
        grid_sync();
    }
}

// ---------------- final FC (O=1) ----------------
__global__ void fc_kernel(const float* __restrict__ fc_w, const float* __restrict__ fc_b,
                          float* __restrict__ out)
{
    const float* h = g_h1[TT & 1];
    const int warp = (blockIdx.x * blockDim.x + threadIdx.x) >> 5;
    const int lane = threadIdx.x & 31;
    if (warp >= BB) return;
    float s = 0.f;
    for (int k = lane; k < HH; k += 32) s += h[warp * HH + k] * fc_w[k];
#pragma unroll
    for (int off = 16; off; off >>= 1) s += __shfl_xor_sync(0xffffffffu, s, off);
    if (lane == 0) out[warp] = s + fc_b[0];
}

// ---------------- launch ----------------
extern "C" void kernel_launch(void* const* d_in, const int* in_sizes, int n_in,
                              void* d_out, int out_size)
{
    const float* x     = (const float*)d_in[0];
    const float* w_ih0 = (const float*)d_in[1];
    const float* w_hh0 = (const float*)d_in[2];
    const float* b_ih0 = (const float*)d_in[3];
    const float* b_hh0 = (const float*)d_in[4];
    const float* w_ih1 = (const float*)d_in[5];
    const float* w_hh1 = (const float*)d_in[6];
    const float* b_ih1 = (const float*)d_in[7];
    const float* b_hh1 = (const float*)d_in[8];
    const float* fc_w  = (const float*)d_in[9];
    const float* fc_b  = (const float*)d_in[10];
    float* out = (float*)d_out;

    pack_init<<<512, 256>>>(w_ih0, w_hh0, b_ih0, b_hh0, w_ih1, w_hh1, b_ih1, b_hh1);
    lstm_persistent<<<NBLK, 256>>>(x);
    fc_kernel<<<BB * 32 / 256, 256>>>(fc_w, fc_b, out);
}

// round 5
// speedup vs baseline: 1.6610x; 1.5472x over previous
#include <cuda_runtime.h>
#include <cuda_bf16.h>
#include <cstddef>
#include <cstdint>

#define BB 1024   // batch
#define TT 512    // time steps
#define II 64     // input dim
#define HH 256    // hidden dim
#define G4 1024   // 4*H
#define NBLK 128  // persistent CTAs
#define KC0 (II + HH)    // 320
#define KC1 (HH + HH)    // 512
#define KB0 (KC0 / 16)   // 20
#define KB1 (KC1 / 16)   // 32

// ---------------- persistent device scratch ----------------
// Prepacked weights in per-lane B-fragment order, bf16.
// Layout: slice s (8) | seg (0=hi,1=lo) | kblk (KC/16) | nfrag (16) | 32 units * 4 bf16
__device__ __align__(16) __nv_bfloat16 g_Wp0[8 * 128 * 2 * KC0];
__device__ __align__(16) __nv_bfloat16 g_Wp1[8 * 128 * 2 * KC1];
__device__ float g_b0[G4];
__device__ float g_b1[G4];
// x transposed to [t][b][k], split hi/lo bf16
__device__ __align__(16) __nv_bfloat16 g_xhi[TT * BB * II];
__device__ __align__(16) __nv_bfloat16 g_xlo[TT * BB * II];
// hidden states, split hi/lo bf16, ping-pong
__device__ __align__(16) __nv_bfloat16 g_h0hi[2][BB * HH];
__device__ __align__(16) __nv_bfloat16 g_h0lo[2][BB * HH];
__device__ __align__(16) __nv_bfloat16 g_h1hi[2][BB * HH];
__device__ __align__(16) __nv_bfloat16 g_h1lo[2][BB * HH];
__device__ float g_c0[BB * HH];
__device__ float g_c1[BB * HH];
__device__ unsigned g_bar_count;
__device__ unsigned g_bar_gen;

// ---------------- weight fragment packing ----------------
__device__ void packW(__nv_bfloat16* __restrict__ Wp,
                      const float* __restrict__ wih, const float* __restrict__ whh,
                      int KIN, int KC, int KCb, int tid, int stride)
{
    const int nunits = 8 * 2 * KCb * 16 * 32;
    for (int idx = tid; idx < nunits; idx += stride) {
        const int u = idx & 31;
        const int nfrag = (idx >> 5) & 15;
        int rest = idx >> 9;
        const int kb = rest % KCb; rest /= KCb;
        const int seg = rest & 1;
        const int s = rest >> 1;
        const int col = u >> 2, kp = u & 3;
        const int np = nfrag * 8 + col;
        const int gate = np & 3, nh = np >> 2;
        const int row = gate * HH + s * 32 + nh;
        const size_t base = (size_t)s * 128 * 2 * KC +
                            (size_t)(((seg * KCb + kb) * 16 + nfrag) * 128) + u * 4;
        const int kks[4] = { kb * 16 + 2 * kp, kb * 16 + 2 * kp + 1,
                             kb * 16 + 2 * kp + 8, kb * 16 + 2 * kp + 9 };
#pragma unroll
        for (int j = 0; j < 4; ++j) {
            const int kk = kks[j];
            const float wv = (kk < KIN) ? wih[row * KIN + kk] : whh[row * HH + (kk - KIN)];
            const __nv_bfloat16 hi = __float2bfloat16_rn(wv);
            Wp[base + j] = (seg == 0) ? hi
                         : __float2bfloat16_rn(wv - __bfloat162float(hi));
        }
    }
}

__global__ void pack_init(const float* __restrict__ x,
                          const float* __restrict__ w_ih0, const float* __restrict__ w_hh0,
                          const float* __restrict__ b_ih0, const float* __restrict__ b_hh0,
                          const float* __restrict__ w_ih1, const float* __restrict__ w_hh1,
                          const float* __restrict__ b_ih1, const float* __restrict__ b_hh1)
{
    const int tid = blockIdx.x * blockDim.x + threadIdx.x;
    const int stride = gridDim.x * blockDim.x;

    packW(g_Wp0, w_ih0, w_hh0, II, KC0, KB0, tid, stride);
    packW(g_Wp1, w_ih1, w_hh1, HH, KC1, KB1, tid, stride);

    for (int idx = tid; idx < G4; idx += stride) {
        g_b0[idx] = b_ih0[idx] + b_hh0[idx];
        g_b1[idx] = b_ih1[idx] + b_hh1[idx];
    }
    // x: [b][t][k] -> [t][b][k], hi/lo split (dest-major for coalesced writes)
    for (int idx = tid; idx < TT * BB * II; idx += stride) {
        const int k = idx % II;
        const int b = (idx / II) % BB;
        const int t = idx / (II * BB);
        const float v = x[((size_t)b * TT + t) * II + k];
        const __nv_bfloat16 hi = __float2bfloat16_rn(v);
        g_xhi[idx] = hi;
        g_xlo[idx] = __float2bfloat16_rn(v - __bfloat162float(hi));
    }
    const __nv_bfloat16 z = __float2bfloat16_rn(0.f);
    for (int idx = tid; idx < BB * HH; idx += stride) {
        g_h0hi[0][idx] = z; g_h0lo[0][idx] = z;
        g_h1hi[0][idx] = z; g_h1lo[0][idx] = z;
        g_c0[idx] = 0.f;    g_c1[idx] = 0.f;
    }
    if (tid == 0) { g_bar_count = 0; g_bar_gen = 0; }
}

// ---------------- grid-wide barrier ----------------
__device__ __forceinline__ void grid_sync()
{
    __threadfence();
    __syncthreads();
    if (threadIdx.x == 0) {
        unsigned gen = *(volatile unsigned*)&g_bar_gen;
        if (atomicAdd(&g_bar_count, 1u) == (unsigned)(NBLK - 1)) {
            *(volatile unsigned*)&g_bar_count = 0u;
            __threadfence();
            *(volatile unsigned*)&g_bar_gen = gen + 1u;
        } else {
            while (*(volatile unsigned*)&g_bar_gen == gen) { __nanosleep(64); }
        }
    }
    __syncthreads();
}

// ---------------- mma wrapper ----------------
__device__ __forceinline__ void mma16816(float* d,
                                         uint32_t a0, uint32_t a1, uint32_t a2, uint32_t a3,
                                         uint32_t b0, uint32_t b1)
{
    asm volatile("mma.sync.aligned.m16n8k16.row.col.f32.bf16.bf16.f32 "
                 "{%0,%1,%2,%3}, {%4,%5,%6,%7}, {%8,%9}, {%0,%1,%2,%3};\n"
                 : "+f"(d[0]), "+f"(d[1]), "+f"(d[2]), "+f"(d[3])
                 : "r"(a0), "r"(a1), "r"(a2), "r"(a3), "r"(b0), "r"(b1));
}

__device__ __forceinline__ float sigm(float z) { return 1.f / (1.f + __expf(-z)); }
__device__ __forceinline__ float tanh_fast(float z) { return 2.f / (1.f + __expf(-2.f * z)) - 1.f; }

// ---------------- one [64 x (32 hidden)] LSTM tile via bf16 hi/lo MMA ----------------
// A sources (pre-split bf16): a0* covers k < KIN (row stride a0stride), a1* covers
// k >= KIN (row stride HH). Wp: prepacked fragments for this layer. Smem: 64x40
// bf16 chunks (pitch 80B), hi and lo.
template <int KIN>
__device__ __forceinline__ void lstm_tile_mma(
    const __nv_bfloat16* __restrict__ a0hi, const __nv_bfloat16* __restrict__ a0lo, int a0stride,
    const __nv_bfloat16* __restrict__ a1hi, const __nv_bfloat16* __restrict__ a1lo,
    const __nv_bfloat16* __restrict__ Wp, const float* __restrict__ bias,
    float* __restrict__ c,
    __nv_bfloat16* __restrict__ outhi, __nv_bfloat16* __restrict__ outlo,
    char* __restrict__ sAhi, char* __restrict__ sAlo,
    int m0, int s)
{
    constexpr int KC = KIN + HH;
    constexpr int KCb = KC / 16;
    constexpr int NCH = KC / 32;

    const int tid = threadIdx.x;
    const int lane = tid & 31;
    const int w = tid >> 5;
    const int mwb = (w & 3) * 16;   // m-block within tile
    const int nwb = w >> 2;         // 0/1: 16-hidden-col half

    float acc[8][4];
#pragma unroll
    for (int nb = 0; nb < 8; ++nb)
#pragma unroll
        for (int j = 0; j < 4; ++j) acc[nb][j] = 0.f;

    // chunk loader mapping: 64 rows x 32 bf16; thread -> (row, 16B quarter)
    const int lrow = tid >> 2;
    const int lq = tid & 3;
    const int mg = m0 + lrow;

    const __nv_bfloat16* wpc = Wp + (size_t)s * 128 * 2 * KC
                                  + (size_t)(nwb * 8) * 128 + lane * 4;

    // preload chunk 0
    uint4 phi, plo;
    {
        const __nv_bfloat16* shi = (0 < KIN) ? a0hi : a1hi;
        const __nv_bfloat16* slo = (0 < KIN) ? a0lo : a1lo;
        const int str = (0 < KIN) ? a0stride : HH;
        phi = *(const uint4*)(shi + (size_t)mg * str + lq * 8);
        plo = *(const uint4*)(slo + (size_t)mg * str + lq * 8);
    }

    for (int kb2 = 0; kb2 < NCH; ++kb2) {
        *(uint4*)(sAhi + lrow * 80 + lq * 16) = phi;
        *(uint4*)(sAlo + lrow * 80 + lq * 16) = plo;
        __syncthreads();

        if (kb2 + 1 < NCH) {
            const int k0 = (kb2 + 1) * 32;
            const __nv_bfloat16* shi; const __nv_bfloat16* slo; int str, koff;
            if (k0 < KIN) { shi = a0hi; slo = a0lo; str = a0stride; koff = k0; }
            else          { shi = a1hi; slo = a1lo; str = HH;       koff = k0 - KIN; }
            phi = *(const uint4*)(shi + (size_t)mg * str + koff + lq * 8);
            plo = *(const uint4*)(slo + (size_t)mg * str + koff + lq * 8);
        }

#pragma unroll
        for (int ks = 0; ks < 2; ++ks) {
            const int kb = kb2 * 2 + ks;
            const int abase = (mwb + (lane >> 2)) * 80 + (lane & 3) * 4 + ks * 32;
            const uint32_t ah0 = *(const uint32_t*)(sAhi + abase);
            const uint32_t ah1 = *(const uint32_t*)(sAhi + abase + 8 * 80);
            const uint32_t ah2 = *(const uint32_t*)(sAhi + abase + 16);
            const uint32_t ah3 = *(const uint32_t*)(sAhi + abase + 8 * 80 + 16);
            const uint32_t al0 = *(const uint32_t*)(sAlo + abase);
            const uint32_t al1 = *(const uint32_t*)(sAlo + abase + 8 * 80);
            const uint32_t al2 = *(const uint32_t*)(sAlo + abase + 16);
            const uint32_t al3 = *(const uint32_t*)(sAlo + abase + 8 * 80 + 16);

            const __nv_bfloat16* bhi = wpc + (size_t)(kb * 16) * 128;
            const __nv_bfloat16* blo = wpc + (size_t)((KCb + kb) * 16) * 128;
#pragma unroll
            for (int nb = 0; nb < 8; ++nb) {
                const uint2 bw = *(const uint2*)(bhi + nb * 128);
                mma16816(acc[nb], ah0, ah1, ah2, ah3, bw.x, bw.y);
                mma16816(acc[nb], al0, al1, al2, al3, bw.x, bw.y);
            }
#pragma unroll
            for (int nb = 0; nb < 8; ++nb) {
                const uint2 bw = *(const uint2*)(blo + nb * 128);
                mma16816(acc[nb], ah0, ah1, ah2, ah3, bw.x, bw.y);
            }
        }
        __syncthreads();
    }

    // ---- epilogue: exchange gates, apply cell ----
    const int r1 = m0 + mwb + (lane >> 2);
#pragma unroll
    for (int nb = 0; nb < 8; ++nb) {
        const float f0 = acc[nb][0], f1 = acc[nb][1], f2 = acc[nb][2], f3 = acc[nb][3];
        const float p0 = __shfl_xor_sync(0xffffffffu, f0, 1);
        const float p1 = __shfl_xor_sync(0xffffffffu, f1, 1);
        const float p2 = __shfl_xor_sync(0xffffffffu, f2, 1);
        const float p3 = __shfl_xor_sync(0xffffffffu, f3, 1);
        if (!(lane & 1)) {
            // this thread holds gates (i,f); partner held (g,o)
            const int nh = nwb * 16 + nb * 2 + ((lane & 2) >> 1);
            const int n = s * 32 + nh;
            const float bi = bias[n];
            const float bfv = bias[HH + n];
            const float bg = bias[2 * HH + n];
            const float bo = bias[3 * HH + n];
#pragma unroll
            for (int rr = 0; rr < 2; ++rr) {
                const int m = r1 + rr * 8;
                const float zi = (rr ? f2 : f0) + bi;
                const float zf = (rr ? f3 : f1) + bfv;
                const float zg = (rr ? p2 : p0) + bg;
                const float zo = (rr ? p3 : p1) + bo;
                const float ig = sigm(zi), fg = sigm(zf);
                const float gg = tanh_fast(zg), og = sigm(zo);
                const size_t ci = (size_t)m * HH + n;
                const float cn = fg * c[ci] + ig * gg;
                c[ci] = cn;
                const float h = og * tanh_fast(cn);
                const __nv_bfloat16 hi = __float2bfloat16_rn(h);
                outhi[ci] = hi;
                outlo[ci] = __float2bfloat16_rn(h - __bfloat162float(hi));
            }
        }
    }
}

// ---------------- persistent fused LSTM ----------------
// Phase p: layer0 at t=p (p<TT) and layer1 at t=p-1 (p>0), then grid barrier.
// h(t) lives in buf[(t+1)&1]; h(-1)=zeros in buf[0].
__global__ __launch_bounds__(256, 1) void lstm_persistent()
{
    __shared__ __align__(16) char sAhi[64 * 80];
    __shared__ __align__(16) char sAlo[64 * 80];

    const int b = blockIdx.x;
    const int m0 = (b & 15) * 64;
    const int s = b >> 4;   // hidden-col slice 0..7

    for (int p = 0; p <= TT; ++p) {
        if (p < TT) {
            lstm_tile_mma<II>(g_xhi + (size_t)p * BB * II, g_xlo + (size_t)p * BB * II, II,
                              g_h0hi[p & 1], g_h0lo[p & 1],
                              g_Wp0, g_b0, g_c0,
                              g_h0hi[(p + 1) & 1], g_h0lo[(p + 1) & 1],
                              sAhi, sAlo, m0, s);
        }
        if (p > 0) {
            lstm_tile_mma<HH>(g_h0hi[p & 1], g_h0lo[p & 1], HH,
                              g_h1hi[(p - 1) & 1], g_h1lo[(p - 1) & 1],
                              g_Wp1, g_b1, g_c1,
                              g_h1hi[p & 1], g_h1lo[p & 1],
                              sAhi, sAlo, m0, s);
        }
        grid_sync();
    }
}

// ---------------- final FC (O=1) ----------------
__global__ void fc_kernel(const float* __restrict__ fc_w, const float* __restrict__ fc_b,
                          float* __restrict__ out)
{
    const __nv_bfloat16* hhi = g_h1hi[TT & 1];
    const __nv_bfloat16* hlo = g_h1lo[TT & 1];
    const int warp = (blockIdx.x * blockDim.x + threadIdx.x) >> 5;
    const int lane = threadIdx.x & 31;
    if (warp >= BB) return;
    float sum = 0.f;
    for (int k = lane; k < HH; k += 32) {
        const float h = __bfloat162float(hhi[warp * HH + k]) + __bfloat162float(hlo[warp * HH + k]);
        sum += h * fc_w[k];
    }
#pragma unroll
    for (int off = 16; off; off >>= 1) sum += __shfl_xor_sync(0xffffffffu, sum, off);
    if (lane == 0) out[warp] = sum + fc_b[0];
}

// ---------------- launch ----------------
extern "C" void kernel_launch(void* const* d_in, const int* in_sizes, int n_in,
                              void* d_out, int out_size)
{
    const float* x     = (const float*)d_in[0];
    const float* w_ih0 = (const float*)d_in[1];
    const float* w_hh0 = (const float*)d_in[2];
    const float* b_ih0 = (const float*)d_in[3];
    const float* b_hh0 = (const float*)d_in[4];
    const float* w_ih1 = (const float*)d_in[5];
    const float* w_hh1 = (const float*)d_in[6];
    const float* b_ih1 = (const float*)d_in[7];
    const float* b_hh1 = (const float*)d_in[8];
    const float* fc_w  = (const float*)d_in[9];
    const float* fc_b  = (const float*)d_in[10];
    float* out = (float*)d_out;

    pack_init<<<2048, 256>>>(x, w_ih0, w_hh0, b_ih0, b_hh0,
                             w_ih1, w_hh1, b_ih1, b_hh1);
    lstm_persistent<<<NBLK, 256>>>();
    fc_kernel<<<BB * 32 / 256, 256>>>(fc_w, fc_b, out);
}

// round 7
// speedup vs baseline: 2.3167x; 1.3947x over previous
#include <cuda_runtime.h>
#include <cuda_fp16.h>
#include <cstddef>
#include <cstdint>

#define BB 1024   // batch
#define TT 512    // time steps
#define II 64     // input dim
#define HH 256    // hidden dim
#define G4 1024   // 4*H
#define NBLK 128  // persistent CTAs
#define KC0 (II + HH)    // 320
#define KC1 (HH + HH)    // 512
#define KB0 (KC0 / 16)   // 20
#define KB1 (KC1 / 16)   // 32

// ---------------- persistent device scratch ----------------
// Prepacked weights in per-lane B-fragment order, fp16.
// Layout: slice s (8) | kblk (KC/16) | nfrag (16) | 32 units * 4 halves
__device__ __align__(16) __half g_Wp0[8 * 128 * KC0];
__device__ __align__(16) __half g_Wp1[8 * 128 * KC1];
__device__ float g_b0[G4];
__device__ float g_b1[G4];
// x transposed to [t][b][k], fp16
__device__ __align__(16) __half g_xh[(size_t)TT * BB * II];
// hidden states fp16, ping-pong
__device__ __align__(16) __half g_h0[2][BB * HH];
__device__ __align__(16) __half g_h1[2][BB * HH];
__device__ float g_c0[BB * HH];
__device__ float g_c1[BB * HH];
__device__ unsigned g_bar_count;
__device__ unsigned g_bar_gen;

// ---------------- weight fragment packing ----------------
__device__ void packW(__half* __restrict__ Wp,
                      const float* __restrict__ wih, const float* __restrict__ whh,
                      int KIN, int KC, int KCb, int tid, int stride)
{
    const int nunits = 8 * KCb * 16 * 32;
    for (int idx = tid; idx < nunits; idx += stride) {
        const int u = idx & 31;
        const int nfrag = (idx >> 5) & 15;
        int rest = idx >> 9;
        const int kb = rest % KCb;
        const int s = rest / KCb;
        const int col = u >> 2, kp = u & 3;
        const int np = nfrag * 8 + col;
        const int gate = np & 3, nh = np >> 2;
        const int row = gate * HH + s * 32 + nh;
        const size_t base = (size_t)s * 128 * KC +
                            (size_t)((kb * 16 + nfrag) * 128) + u * 4;
        const int kks[4] = { kb * 16 + 2 * kp, kb * 16 + 2 * kp + 1,
                             kb * 16 + 2 * kp + 8, kb * 16 + 2 * kp + 9 };
#pragma unroll
        for (int j = 0; j < 4; ++j) {
            const int kk = kks[j];
            const float wv = (kk < KIN) ? wih[row * KIN + kk] : whh[row * HH + (kk - KIN)];
            Wp[base + j] = __float2half_rn(wv);
        }
    }
}

__global__ void pack_init(const float* __restrict__ x,
                          const float* __restrict__ w_ih0, const float* __restrict__ w_hh0,
                          const float* __restrict__ b_ih0, const float* __restrict__ b_hh0,
                          const float* __restrict__ w_ih1, const float* __restrict__ w_hh1,
                          const float* __restrict__ b_ih1, const float* __restrict__ b_hh1)
{
    const int tid = blockIdx.x * blockDim.x + threadIdx.x;
    const int stride = gridDim.x * blockDim.x;

    packW(g_Wp0, w_ih0, w_hh0, II, KC0, KB0, tid, stride);
    packW(g_Wp1, w_ih1, w_hh1, HH, KC1, KB1, tid, stride);

    for (int idx = tid; idx < G4; idx += stride) {
        g_b0[idx] = b_ih0[idx] + b_hh0[idx];
        g_b1[idx] = b_ih1[idx] + b_hh1[idx];
    }
    // x: [b][t][k] -> [t][b][k] fp16
    for (size_t idx = tid; idx < (size_t)TT * BB * II; idx += stride) {
        const int k = idx % II;
        const int b = (idx / II) % BB;
        const int t = idx / ((size_t)II * BB);
        g_xh[idx] = __float2half_rn(x[((size_t)b * TT + t) * II + k]);
    }
    const __half z = __float2half_rn(0.f);
    for (int idx = tid; idx < BB * HH; idx += stride) {
        g_h0[0][idx] = z;
        g_h1[0][idx] = z;
        g_c0[idx] = 0.f;
        g_c1[idx] = 0.f;
    }
    if (tid == 0) { g_bar_count = 0; g_bar_gen = 0; }
}

// ---------------- grid-wide barrier ----------------
__device__ __forceinline__ void grid_sync()
{
    __threadfence();
    __syncthreads();
    if (threadIdx.x == 0) {
        unsigned gen = *(volatile unsigned*)&g_bar_gen;
        if (atomicAdd(&g_bar_count, 1u) == (unsigned)(NBLK - 1)) {
            *(volatile unsigned*)&g_bar_count = 0u;
            __threadfence();
            *(volatile unsigned*)&g_bar_gen = gen + 1u;
        } else {
            while (*(volatile unsigned*)&g_bar_gen == gen) { __nanosleep(64); }
        }
    }
    __syncthreads();
}

// ---------------- mma wrapper ----------------
__device__ __forceinline__ void mma16816(float* d,
                                         uint32_t a0, uint32_t a1, uint32_t a2, uint32_t a3,
                                         uint32_t b0, uint32_t b1)
{
    asm volatile("mma.sync.aligned.m16n8k16.row.col.f32.f16.f16.f32 "
                 "{%0,%1,%2,%3}, {%4,%5,%6,%7}, {%8,%9}, {%0,%1,%2,%3};\n"
                 : "+f"(d[0]), "+f"(d[1]), "+f"(d[2]), "+f"(d[3])
                 : "r"(a0), "r"(a1), "r"(a2), "r"(a3), "r"(b0), "r"(b1));
}

__device__ __forceinline__ float sigm(float z) { return 1.f / (1.f + __expf(-z)); }
__device__ __forceinline__ float tanh_fast(float z) { return 2.f / (1.f + __expf(-2.f * z)) - 1.f; }

// ---------------- one [64 x (32 hidden)] LSTM tile via fp16 MMA ----------------
// a0: k < KIN (row stride a0stride); a1: k >= KIN (row stride HH).
// Wp: prepacked fragments. sA: 64-row x 80B-pitch chunk buffer (32 k fp16/row).
template <int KIN>
__device__ __forceinline__ void lstm_tile_mma(
    const __half* __restrict__ a0, int a0stride,
    const __half* __restrict__ a1,
    const __half* __restrict__ Wp, const float* __restrict__ bias,
    float* __restrict__ c, __half* __restrict__ outh,
    char* __restrict__ sA,
    int m0, int s)
{
    constexpr int KC = KIN + HH;
    constexpr int KCb = KC / 16;
    constexpr int NCH = KC / 32;

    const int tid = threadIdx.x;
    const int lane = tid & 31;
    const int w = tid >> 5;
    const int mwb = (w & 3) * 16;   // m-block within tile
    const int nwb = w >> 2;         // 0/1: 16-hidden-col half

    float acc[8][4];
#pragma unroll
    for (int nb = 0; nb < 8; ++nb)
#pragma unroll
        for (int j = 0; j < 4; ++j) acc[nb][j] = 0.f;

    // chunk loader mapping: 64 rows x 32 fp16 (64B) = 4 x 16B quarters
    const int lrow = tid >> 2;
    const int lq = tid & 3;
    const int mg = m0 + lrow;

    const __half* wpc = Wp + (size_t)s * 128 * KC + (size_t)(nwb * 8) * 128 + lane * 4;

    // preload chunk 0
    uint4 ph;
    {
        const __half* src = (0 < KIN) ? a0 : a1;
        const int str = (0 < KIN) ? a0stride : HH;
        ph = *(const uint4*)(src + (size_t)mg * str + lq * 8);
    }

    for (int kb2 = 0; kb2 < NCH; ++kb2) {
        *(uint4*)(sA + lrow * 80 + lq * 16) = ph;
        __syncthreads();

        if (kb2 + 1 < NCH) {
            const int k0 = (kb2 + 1) * 32;
            const __half* src; int str, koff;
            if (k0 < KIN) { src = a0; str = a0stride; koff = k0; }
            else          { src = a1; str = HH;       koff = k0 - KIN; }
            ph = *(const uint4*)(src + (size_t)mg * str + koff + lq * 8);
        }

#pragma unroll
        for (int ks = 0; ks < 2; ++ks) {
            const int kb = kb2 * 2 + ks;
            const int abase = (mwb + (lane >> 2)) * 80 + (lane & 3) * 4 + ks * 32;
            const uint32_t a0r = *(const uint32_t*)(sA + abase);
            const uint32_t a1r = *(const uint32_t*)(sA + abase + 8 * 80);
            const uint32_t a2r = *(const uint32_t*)(sA + abase + 16);
            const uint32_t a3r = *(const uint32_t*)(sA + abase + 8 * 80 + 16);

            const __half* bp = wpc + (size_t)(kb * 16) * 128;
#pragma unroll
            for (int nb = 0; nb < 8; ++nb) {
                const uint2 bw = *(const uint2*)(bp + nb * 128);
                mma16816(acc[nb], a0r, a1r, a2r, a3r, bw.x, bw.y);
            }
        }
        __syncthreads();
    }

    // ---- epilogue: exchange gates, apply cell ----
    const int r1 = m0 + mwb + (lane >> 2);
#pragma unroll
    for (int nb = 0; nb < 8; ++nb) {
        const float f0 = acc[nb][0], f1 = acc[nb][1], f2 = acc[nb][2], f3 = acc[nb][3];
        const float p0 = __shfl_xor_sync(0xffffffffu, f0, 1);
        const float p1 = __shfl_xor_sync(0xffffffffu, f1, 1);
        const float p2 = __shfl_xor_sync(0xffffffffu, f2, 1);
        const float p3 = __shfl_xor_sync(0xffffffffu, f3, 1);
        if (!(lane & 1)) {
            // this thread holds gates (i,f); partner held (g,o)
            const int nh = nwb * 16 + nb * 2 + ((lane & 2) >> 1);
            const int n = s * 32 + nh;
            const float bi = bias[n];
            const float bfv = bias[HH + n];
            const float bg = bias[2 * HH + n];
            const float bo = bias[3 * HH + n];
#pragma unroll
            for (int rr = 0; rr < 2; ++rr) {
                const int m = r1 + rr * 8;
                const float zi = (rr ? f2 : f0) + bi;
                const float zf = (rr ? f3 : f1) + bfv;
                const float zg = (rr ? p2 : p0) + bg;
                const float zo = (rr ? p3 : p1) + bo;
                const float ig = sigm(zi), fg = sigm(zf);
                const float gg = tanh_fast(zg), og = sigm(zo);
                const size_t ci = (size_t)m * HH + n;
                const float cn = fg * c[ci] + ig * gg;
                c[ci] = cn;
                outh[ci] = __float2half_rn(og * tanh_fast(cn));
            }
        }
    }
}

// ---------------- persistent fused LSTM ----------------
// Phase p: layer0 at t=p (p<TT) and layer1 at t=p-1 (p>0), then grid barrier.
// h(t) lives in buf[(t+1)&1]; h(-1)=zeros in buf[0].
__global__ __launch_bounds__(256, 1) void lstm_persistent()
{
    __shared__ __align__(16) char sA[64 * 80];

    const int b = blockIdx.x;
    const int m0 = (b & 15) * 64;
    const int s = b >> 4;   // hidden-col slice 0..7

    for (int p = 0; p <= TT; ++p) {
        if (p < TT) {
            lstm_tile_mma<II>(g_xh + (size_t)p * BB * II, II,
                              g_h0[p & 1],
                              g_Wp0, g_b0, g_c0, g_h0[(p + 1) & 1],
                              sA, m0, s);
        }
        if (p > 0) {
            lstm_tile_mma<HH>(g_h0[p & 1], HH,
                              g_h1[(p - 1) & 1],
                              g_Wp1, g_b1, g_c1, g_h1[p & 1],
                              sA, m0, s);
        }
        grid_sync();
    }
}

// ---------------- final FC (O=1) ----------------
__global__ void fc_kernel(const float* __restrict__ fc_w, const float* __restrict__ fc_b,
                          float* __restrict__ out)
{
    const __half* h = g_h1[TT & 1];
    const int warp = (blockIdx.x * blockDim.x + threadIdx.x) >> 5;
    const int lane = threadIdx.x & 31;
    if (warp >= BB) return;
    float sum = 0.f;
    for (int k = lane; k < HH; k += 32)
        sum += __half2float(h[warp * HH + k]) * fc_w[k];
#pragma unroll
    for (int off = 16; off; off >>= 1) sum += __shfl_xor_sync(0xffffffffu, sum, off);
    if (lane == 0) out[warp] = sum + fc_b[0];
}

// ---------------- launch ----------------
extern "C" void kernel_launch(void* const* d_in, const int* in_sizes, int n_in,
                              void* d_out, int out_size)
{
    const float* x     = (const float*)d_in[0];
    const float* w_ih0 = (const float*)d_in[1];
    const float* w_hh0 = (const float*)d_in[2];
    const float* b_ih0 = (const float*)d_in[3];
    const float* b_hh0 = (const float*)d_in[4];
    const float* w_ih1 = (const float*)d_in[5];
    const float* w_hh1 = (const float*)d_in[6];
    const float* b_ih1 = (const float*)d_in[7];
    const float* b_hh1 = (const float*)d_in[8];
    const float* fc_w  = (const float*)d_in[9];
    const float* fc_b  = (const float*)d_in[10];
    float* out = (float*)d_out;

    pack_init<<<2048, 256>>>(x, w_ih0, w_hh0, b_ih0, b_hh0,
                             w_ih1, w_hh1, b_ih1, b_hh1);
    lstm_persistent<<<NBLK, 256>>>();
    fc_kernel<<<BB * 32 / 256, 256>>>(fc_w, fc_b, out);
}

// round 8
// speedup vs baseline: 3.4378x; 1.4839x over previous
#include <cuda_runtime.h>
#include <cuda_fp16.h>
#include <cstddef>
#include <cstdint>

#define BB 1024   // batch
#define TT 512    // time steps
#define II 64     // input dim
#define HH 256    // hidden dim
#define G4 1024   // 4*H
#define NBLK 128  // 16 m-tiles x 8 slices
#define KC0 (II + HH)    // 320
#define KC1 (HH + HH)    // 512
#define KB0 (KC0 / 16)   // 20
#define KB1 (KC1 / 16)   // 32

// ---- smem layout (bytes) ----
#define SM_W0 0               // 81920  : W0 slice fragments
#define SM_W1 81920           // 131072 : W1 slice fragments
#define SM_A  212992          // 2 x 5120 : A chunk double buffer (64 rows x 80B)
#define SM_B0 223232          // 4096 : bias0
#define SM_B1 227328          // 4096 : bias1
#define SMEM_TOTAL 231424

// ---------------- persistent device scratch ----------------
// Prepacked weights, per-lane B-fragment order, fp16.
// slice s (8) | kblk | nfrag (16) | 32 lanes x 4 halves (8B)
__device__ __align__(16) __half g_Wp0[8 * 128 * KC0];
__device__ __align__(16) __half g_Wp1[8 * 128 * KC1];
__device__ float g_b0[G4];
__device__ float g_b1[G4];
__device__ __align__(16) __half g_xh[(size_t)TT * BB * II];  // [t][b][k]
__device__ __align__(16) __half g_h0[2][BB * HH];
__device__ __align__(16) __half g_h1[2][BB * HH];
__device__ float g_c0[BB * HH];
__device__ float g_c1[BB * HH];
// per-m-group barriers (16 groups of 8 CTAs), padded to 128B lines
__device__ unsigned g_bar_count[16 * 32];
__device__ unsigned g_bar_gen[16 * 32];

// ---------------- weight fragment packing ----------------
__device__ void packW(__half* __restrict__ Wp,
                      const float* __restrict__ wih, const float* __restrict__ whh,
                      int KIN, int KC, int KCb, int tid, int stride)
{
    const int nunits = 8 * KCb * 16 * 32;
    for (int idx = tid; idx < nunits; idx += stride) {
        const int u = idx & 31;
        const int nfrag = (idx >> 5) & 15;
        int rest = idx >> 9;
        const int kb = rest % KCb;
        const int s = rest / KCb;
        const int col = u >> 2, kp = u & 3;
        const int np = nfrag * 8 + col;
        const int gate = np & 3, nh = np >> 2;
        const int row = gate * HH + s * 32 + nh;
        const size_t base = (size_t)s * 128 * KC +
                            (size_t)((kb * 16 + nfrag) * 128) + u * 4;
        const int kks[4] = { kb * 16 + 2 * kp, kb * 16 + 2 * kp + 1,
                             kb * 16 + 2 * kp + 8, kb * 16 + 2 * kp + 9 };
#pragma unroll
        for (int j = 0; j < 4; ++j) {
            const int kk = kks[j];
            const float wv = (kk < KIN) ? wih[row * KIN + kk] : whh[row * HH + (kk - KIN)];
            Wp[base + j] = __float2half_rn(wv);
        }
    }
}

__global__ void pack_init(const float* __restrict__ x,
                          const float* __restrict__ w_ih0, const float* __restrict__ w_hh0,
                          const float* __restrict__ b_ih0, const float* __restrict__ b_hh0,
                          const float* __restrict__ w_ih1, const float* __restrict__ w_hh1,
                          const float* __restrict__ b_ih1, const float* __restrict__ b_hh1)
{
    const int tid = blockIdx.x * blockDim.x + threadIdx.x;
    const int stride = gridDim.x * blockDim.x;

    packW(g_Wp0, w_ih0, w_hh0, II, KC0, KB0, tid, stride);
    packW(g_Wp1, w_ih1, w_hh1, HH, KC1, KB1, tid, stride);

    for (int idx = tid; idx < G4; idx += stride) {
        g_b0[idx] = b_ih0[idx] + b_hh0[idx];
        g_b1[idx] = b_ih1[idx] + b_hh1[idx];
    }
    for (size_t idx = tid; idx < (size_t)TT * BB * II; idx += stride) {
        const int k = idx % II;
        const int b = (idx / II) % BB;
        const int t = idx / ((size_t)II * BB);
        g_xh[idx] = __float2half_rn(x[((size_t)b * TT + t) * II + k]);
    }
    const __half z = __float2half_rn(0.f);
    for (int idx = tid; idx < BB * HH; idx += stride) {
        g_h0[0][idx] = z;
        g_h1[0][idx] = z;
        g_c0[idx] = 0.f;
        g_c1[idx] = 0.f;
    }
    for (int idx = tid; idx < 16 * 32; idx += stride) {
        g_bar_count[idx] = 0;
        g_bar_gen[idx] = 0;
    }
}

// ---------------- per-m-group barrier (8 CTAs) ----------------
__device__ __forceinline__ void group_sync(int grp)
{
    __threadfence();
    __syncthreads();
    if (threadIdx.x == 0) {
        volatile unsigned* genp = &g_bar_gen[grp * 32];
        const unsigned gen = *genp;
        if (atomicAdd(&g_bar_count[grp * 32], 1u) == 7u) {
            *(volatile unsigned*)&g_bar_count[grp * 32] = 0u;
            __threadfence();
            *genp = gen + 1u;
        } else {
            while (*genp == gen) {}
        }
    }
    __syncthreads();
}

// ---------------- mma wrapper ----------------
__device__ __forceinline__ void mma16816(float* d,
                                         uint32_t a0, uint32_t a1, uint32_t a2, uint32_t a3,
                                         uint32_t b0, uint32_t b1)
{
    asm volatile("mma.sync.aligned.m16n8k16.row.col.f32.f16.f16.f32 "
                 "{%0,%1,%2,%3}, {%4,%5,%6,%7}, {%8,%9}, {%0,%1,%2,%3};\n"
                 : "+f"(d[0]), "+f"(d[1]), "+f"(d[2]), "+f"(d[3])
                 : "r"(a0), "r"(a1), "r"(a2), "r"(a3), "r"(b0), "r"(b1));
}

__device__ __forceinline__ float sigm(float z) { return 1.f / (1.f + __expf(-z)); }
__device__ __forceinline__ float tanh_fast(float z) { return 2.f / (1.f + __expf(-2.f * z)) - 1.f; }

// chunk source: c 0-1 -> x(p); c 2-9 -> h0(p-1); c 10-17 -> h1(p-2)
__device__ __forceinline__ uint4 load_chunk(int c, int p, int mg, int lq)
{
    const __half* src;
    int str, koff;
    if (c < 2)       { src = g_xh + (size_t)p * BB * II; str = II; koff = c * 32; }
    else if (c < 10) { src = g_h0[p & 1];        str = HH; koff = (c - 2) * 32; }
    else             { src = g_h1[(p - 1) & 1];  str = HH; koff = (c - 10) * 32; }
    return *(const uint4*)(src + (size_t)mg * str + koff + lq * 8);
}

// ---------------- cell epilogue: all 32 lanes, 8 cells each ----------------
__device__ __forceinline__ void cell_epilogue(
    float (*acc)[4], const char* smem_bias, float* __restrict__ cst,
    __half* __restrict__ outh, int m0, int s, int mwb, int nwb, int lane)
{
    const int par = lane & 1;
    const int row = m0 + mwb + (lane >> 2) + par * 8;
    const int nbase = s * 32 + nwb * 16 + ((lane & 2) >> 1);
#pragma unroll
    for (int nb = 0; nb < 8; ++nb) {
        const float f0 = acc[nb][0], f1 = acc[nb][1], f2 = acc[nb][2], f3 = acc[nb][3];
        const float p0 = __shfl_xor_sync(0xffffffffu, f0, 1);
        const float p1 = __shfl_xor_sync(0xffffffffu, f1, 1);
        const float p2 = __shfl_xor_sync(0xffffffffu, f2, 1);
        const float p3 = __shfl_xor_sync(0xffffffffu, f3, 1);
        // even lane: computes its row (r) with own (i,f)=f0,f1, partner (g,o)=p0,p1
        // odd lane: computes row r+8 with partner (i,f)=p2,p3, own (g,o)=f2,f3
        const float zi0 = par ? p2 : f0;
        const float zf0 = par ? p3 : f1;
        const float zg0 = par ? f2 : p0;
        const float zo0 = par ? f3 : p1;
        const int n = nbase + nb * 2;
        const float bi = *(const float*)(smem_bias + n * 4);
        const float bf = *(const float*)(smem_bias + (HH + n) * 4);
        const float bg = *(const float*)(smem_bias + (2 * HH + n) * 4);
        const float bo = *(const float*)(smem_bias + (3 * HH + n) * 4);
        const float ig = sigm(zi0 + bi);
        const float fg = sigm(zf0 + bf);
        const float gg = tanh_fast(zg0 + bg);
        const float og = sigm(zo0 + bo);
        const size_t ci = (size_t)row * HH + n;
        const float cn = fg * cst[ci] + ig * gg;
        cst[ci] = cn;
        outh[ci] = __float2half_rn(og * tanh_fast(cn));
    }
}

// ---------------- persistent fused LSTM ----------------
// Phase p: layer0 t=p (p<TT) + layer1 t=p-1 (p>0) in ONE merged GEMM pass.
// h(t) in buf[(t+1)&1]; h(-1)=zeros in buf[0].
__global__ __launch_bounds__(256, 1) void lstm_persistent()
{
    extern __shared__ __align__(128) char smc[];
    const int tid = threadIdx.x;
    const int lane = tid & 31;
    const int w = tid >> 5;
    const int mwb = (w & 3) * 16;
    const int nwb = w >> 2;
    const int b = blockIdx.x;
    const int m0 = (b & 15) * 64;
    const int s = b >> 4;       // slice 0..7 (32 hidden cols)
    const int grp = b & 15;
    const int lrow = tid >> 2;  // A-loader row
    const int lq = tid & 3;     // A-loader 16B quarter
    const int mg = m0 + lrow;

    // ---- prologue: W slice + biases into SMEM ----
    {
        const uint4* w0s = (const uint4*)((const char*)g_Wp0 + (size_t)s * 81920);
        uint4* w0d = (uint4*)(smc + SM_W0);
        for (int i = tid; i < 81920 / 16; i += 256) w0d[i] = w0s[i];
        const uint4* w1s = (const uint4*)((const char*)g_Wp1 + (size_t)s * 131072);
        uint4* w1d = (uint4*)(smc + SM_W1);
        for (int i = tid; i < 131072 / 16; i += 256) w1d[i] = w1s[i];
        float* b0d = (float*)(smc + SM_B0);
        float* b1d = (float*)(smc + SM_B1);
        for (int i = tid; i < G4; i += 256) { b0d[i] = g_b0[i]; b1d[i] = g_b1[i]; }
    }
    __syncthreads();

    for (int p = 0; p <= TT; ++p) {
        const bool do0 = (p < TT);
        const bool do1 = (p > 0);
        const int cstart = do0 ? 0 : 2;
        const int cend = do1 ? 18 : 10;

        float acc0[8][4], acc1[8][4];
#pragma unroll
        for (int nb = 0; nb < 8; ++nb)
#pragma unroll
            for (int j = 0; j < 4; ++j) { acc0[nb][j] = 0.f; acc1[nb][j] = 0.f; }

        // preload + stage chunk cstart, prefetch cstart+1
        uint4 ph = load_chunk(cstart, p, mg, lq);
        *(uint4*)(smc + SM_A + (cstart & 1) * 5120 + lrow * 80 + lq * 16) = ph;
        if (cstart + 1 < cend) ph = load_chunk(cstart + 1, p, mg, lq);
        __syncthreads();

        for (int c = cstart; c < cend; ++c) {
            if (c + 1 < cend)
                *(uint4*)(smc + SM_A + ((c + 1) & 1) * 5120 + lrow * 80 + lq * 16) = ph;
            if (c + 2 < cend) ph = load_chunk(c + 2, p, mg, lq);

            const char* sAc = smc + SM_A + (c & 1) * 5120;
#pragma unroll
            for (int ks = 0; ks < 2; ++ks) {
                const int abase = (mwb + (lane >> 2)) * 80 + (lane & 3) * 4 + ks * 32;
                const uint32_t a0r = *(const uint32_t*)(sAc + abase);
                const uint32_t a1r = *(const uint32_t*)(sAc + abase + 8 * 80);
                const uint32_t a2r = *(const uint32_t*)(sAc + abase + 16);
                const uint32_t a3r = *(const uint32_t*)(sAc + abase + 8 * 80 + 16);

                if (do0 && c < 10) {
                    const char* bp = smc + SM_W0 +
                        ((c * 2 + ks) * 16 + nwb * 8) * 256 + lane * 8;
#pragma unroll
                    for (int nb = 0; nb < 8; ++nb) {
                        const uint2 bw = *(const uint2*)(bp + nb * 256);
                        mma16816(acc0[nb], a0r, a1r, a2r, a3r, bw.x, bw.y);
                    }
                }
                if (do1 && c >= 2) {
                    const char* bp = smc + SM_W1 +
                        (((c - 2) * 2 + ks) * 16 + nwb * 8) * 256 + lane * 8;
#pragma unroll
                    for (int nb = 0; nb < 8; ++nb) {
                        const uint2 bw = *(const uint2*)(bp + nb * 256);
                        mma16816(acc1[nb], a0r, a1r, a2r, a3r, bw.x, bw.y);
                    }
                }
            }
            __syncthreads();
        }

        // ---- epilogues (register-local accs; no barrier needed before) ----
        if (do0)
            cell_epilogue(acc0, smc + SM_B0, g_c0, g_h0[(p + 1) & 1], m0, s, mwb, nwb, lane);
        if (do1)
            cell_epilogue(acc1, smc + SM_B1, g_c1, g_h1[p & 1], m0, s, mwb, nwb, lane);

        group_sync(grp);
    }
}

// ---------------- final FC (O=1) ----------------
__global__ void fc_kernel(const float* __restrict__ fc_w, const float* __restrict__ fc_b,
                          float* __restrict__ out)
{
    const __half* h = g_h1[TT & 1];
    const int warp = (blockIdx.x * blockDim.x + threadIdx.x) >> 5;
    const int lane = threadIdx.x & 31;
    if (warp >= BB) return;
    float sum = 0.f;
    for (int k = lane; k < HH; k += 32)
        sum += __half2float(h[warp * HH + k]) * fc_w[k];
#pragma unroll
    for (int off = 16; off; off >>= 1) sum += __shfl_xor_sync(0xffffffffu, sum, off);
    if (lane == 0) out[warp] = sum + fc_b[0];
}

// ---------------- launch ----------------
extern "C" void kernel_launch(void* const* d_in, const int* in_sizes, int n_in,
                              void* d_out, int out_size)
{
    const float* x     = (const float*)d_in[0];
    const float* w_ih0 = (const float*)d_in[1];
    const float* w_hh0 = (const float*)d_in[2];
    const float* b_ih0 = (const float*)d_in[3];
    const float* b_hh0 = (const float*)d_in[4];
    const float* w_ih1 = (const float*)d_in[5];
    const float* w_hh1 = (const float*)d_in[6];
    const float* b_ih1 = (const float*)d_in[7];
    const float* b_hh1 = (const float*)d_in[8];
    const float* fc_w  = (const float*)d_in[9];
    const float* fc_b  = (const float*)d_in[10];
    float* out = (float*)d_out;

    cudaFuncSetAttribute(lstm_persistent,
                         cudaFuncAttributeMaxDynamicSharedMemorySize, SMEM_TOTAL);

    pack_init<<<2048, 256>>>(x, w_ih0, w_hh0, b_ih0, b_hh0,
                             w_ih1, w_hh1, b_ih1, b_hh1);
    lstm_persistent<<<NBLK, 256, SMEM_TOTAL>>>();
    fc_kernel<<<BB * 32 / 256, 256>>>(fc_w, fc_b, out);
}

// round 10
// speedup vs baseline: 5.7168x; 1.6629x over previous
#include <cuda_runtime.h>
#include <cuda_fp16.h>
#include <cstddef>
#include <cstdint>

#define BB 1024   // batch
#define TT 512    // time steps
#define II 64     // input dim
#define HH 256    // hidden dim
#define G4 1024   // 4*H
#define NBLK 128  // 16 m-tiles x 8 slices
#define KC0 (II + HH)    // 320
#define KC1 (HH + HH)    // 512
#define KB0 (KC0 / 16)   // 20
#define KB1 (KC1 / 16)   // 32

// ---- smem layout (bytes) ----
#define SM_W0 0               // 81920  : W0 slice fragments
#define SM_W1 81920           // 131072 : W1 slice fragments
#define SM_A  212992          // 2 x 5120 : A chunk double buffer (64 rows x 80B)
#define SM_B0 223232          // 4096 : bias0
#define SM_B1 227328          // 4096 : bias1
#define SMEM_TOTAL 231424

// ---------------- persistent device scratch ----------------
// Prepacked W fragments, fp16. Per (slice, kblk): 4 warp-n quarters x 2 pairs
// x 32 lanes x 16B; a lane's 16B = B-fragments for 2 adjacent n-frags.
__device__ __align__(16) __half g_Wp0[8 * 128 * KC0];
__device__ __align__(16) __half g_Wp1[8 * 128 * KC1];
__device__ float g_b0[G4];
__device__ float g_b1[G4];
__device__ __align__(16) __half g_xh[(size_t)TT * BB * II];  // [t][b][k]
__device__ __align__(16) __half g_h0[2][BB * HH];
__device__ __align__(16) __half g_h1[2][BB * HH];
// per-m-group barriers (16 groups of 8 CTAs), padded lines
__device__ unsigned g_bar_count[16 * 32];
__device__ unsigned g_bar_gen[16 * 32];

// ---------------- weight fragment packing ----------------
__device__ void packW(__half* __restrict__ Wp,
                      const float* __restrict__ wih, const float* __restrict__ whh,
                      int KIN, int KC, int KCb, int tid, int stride)
{
    const int nunits = 8 * KCb * 4 * 2 * 32;   // slices x kblks x wn x pair x lane
    for (int idx = tid; idx < nunits; idx += stride) {
        const int u = idx & 31;
        const int j = (idx >> 5) & 1;
        const int wn = (idx >> 6) & 3;
        int rest = idx >> 8;
        const int kb = rest % KCb;
        const int s = rest / KCb;
        const int col = u >> 2, kp = u & 3;
        const size_t base = (size_t)s * KC * 128 + (size_t)kb * 2048
                          + (wn * 2 + j) * 256 + u * 8;
        const int kbase = kb * 16 + 2 * kp;
        const int kks[4] = { kbase, kbase + 1, kbase + 8, kbase + 9 };
#pragma unroll
        for (int f = 0; f < 2; ++f) {
            const int nfrag = wn * 4 + j * 2 + f;
            const int np = nfrag * 8 + col;
            const int gate = np & 3, nh = np >> 2;
            const int row = gate * HH + s * 32 + nh;
#pragma unroll
            for (int jj = 0; jj < 4; ++jj) {
                const int kk = kks[jj];
                const float wv = (kk < KIN) ? wih[row * KIN + kk]
                                            : whh[row * HH + (kk - KIN)];
                Wp[base + f * 4 + jj] = __float2half_rn(wv);
            }
        }
    }
}

__global__ void pack_init(const float* __restrict__ x,
                          const float* __restrict__ w_ih0, const float* __restrict__ w_hh0,
                          const float* __restrict__ b_ih0, const float* __restrict__ b_hh0,
                          const float* __restrict__ w_ih1, const float* __restrict__ w_hh1,
                          const float* __restrict__ b_ih1, const float* __restrict__ b_hh1)
{
    const int tid = blockIdx.x * blockDim.x + threadIdx.x;
    const int stride = gridDim.x * blockDim.x;

    packW(g_Wp0, w_ih0, w_hh0, II, KC0, KB0, tid, stride);
    packW(g_Wp1, w_ih1, w_hh1, HH, KC1, KB1, tid, stride);

    for (int idx = tid; idx < G4; idx += stride) {
        g_b0[idx] = b_ih0[idx] + b_hh0[idx];
        g_b1[idx] = b_ih1[idx] + b_hh1[idx];
    }
    for (size_t idx = tid; idx < (size_t)TT * BB * II; idx += stride) {
        const int k = idx % II;
        const int b = (idx / II) % BB;
        const int t = idx / ((size_t)II * BB);
        g_xh[idx] = __float2half_rn(x[((size_t)b * TT + t) * II + k]);
    }
    const __half z = __float2half_rn(0.f);
    for (int idx = tid; idx < BB * HH; idx += stride) {
        g_h0[0][idx] = z;
        g_h1[0][idx] = z;
    }
    for (int idx = tid; idx < 16 * 32; idx += stride) {
        g_bar_count[idx] = 0;
        g_bar_gen[idx] = 0;
    }
}

// ---------------- per-m-group barrier (8 CTAs) ----------------
__device__ __forceinline__ void group_sync(int grp)
{
    __threadfence();
    __syncthreads();
    if (threadIdx.x == 0) {
        volatile unsigned* genp = &g_bar_gen[grp * 32];
        const unsigned gen = *genp;
        if (atomicAdd(&g_bar_count[grp * 32], 1u) == 7u) {
            *(volatile unsigned*)&g_bar_count[grp * 32] = 0u;
            __threadfence();
            *genp = gen + 1u;
        } else {
            while (*genp == gen) {}
        }
    }
    __syncthreads();
}

// ---------------- mma wrapper ----------------
__device__ __forceinline__ void mma16816(float* d,
                                         uint32_t a0, uint32_t a1, uint32_t a2, uint32_t a3,
                                         uint32_t b0, uint32_t b1)
{
    asm volatile("mma.sync.aligned.m16n8k16.row.col.f32.f16.f16.f32 "
                 "{%0,%1,%2,%3}, {%4,%5,%6,%7}, {%8,%9}, {%0,%1,%2,%3};\n"
                 : "+f"(d[0]), "+f"(d[1]), "+f"(d[2]), "+f"(d[3])
                 : "r"(a0), "r"(a1), "r"(a2), "r"(a3), "r"(b0), "r"(b1));
}

__device__ __forceinline__ float sigm(float z) { return 1.f / (1.f + __expf(-z)); }
__device__ __forceinline__ float tanh_fast(float z) { return 2.f / (1.f + __expf(-2.f * z)) - 1.f; }

// chunk source: c 0-1 -> x(p); c 2-9 -> h0(p-1); c 10-17 -> h1(p-2)
__device__ __forceinline__ uint2 load_chunk(int c, int p, int mg, int lq)
{
    const __half* src;
    int str, koff;
    if (c < 2)       { src = g_xh + (size_t)p * BB * II; str = II; koff = c * 32; }
    else if (c < 10) { src = g_h0[p & 1];        str = HH; koff = (c - 2) * 32; }
    else             { src = g_h1[(p - 1) & 1];  str = HH; koff = (c - 10) * 32; }
    return *(const uint2*)(src + (size_t)mg * str + koff + lq * 4);
}

// ---------------- cell epilogue: c in registers ----------------
__device__ __forceinline__ void cell_epilogue(
    float (*acc)[4], float* __restrict__ creg, const char* smem_bias,
    __half* __restrict__ outh, int m0, int s, int mwb, int wn, int lane)
{
    const int par = lane & 1;
    const int row = m0 + mwb + (lane >> 2) + par * 8;
    const int nbase = s * 32 + wn * 8 + ((lane & 2) >> 1);
#pragma unroll
    for (int nb = 0; nb < 4; ++nb) {
        const float f0 = acc[nb][0], f1 = acc[nb][1], f2 = acc[nb][2], f3 = acc[nb][3];
        const float p0 = __shfl_xor_sync(0xffffffffu, f0, 1);
        const float p1 = __shfl_xor_sync(0xffffffffu, f1, 1);
        const float p2 = __shfl_xor_sync(0xffffffffu, f2, 1);
        const float p3 = __shfl_xor_sync(0xffffffffu, f3, 1);
        // even lane: row r, own (i,f), partner (g,o); odd lane: row r+8
        const float zi0 = par ? p2 : f0;
        const float zf0 = par ? p3 : f1;
        const float zg0 = par ? f2 : p0;
        const float zo0 = par ? f3 : p1;
        const int n = nbase + nb * 2;
        const float bi = *(const float*)(smem_bias + n * 4);
        const float bf = *(const float*)(smem_bias + (HH + n) * 4);
        const float bg = *(const float*)(smem_bias + (2 * HH + n) * 4);
        const float bo = *(const float*)(smem_bias + (3 * HH + n) * 4);
        const float ig = sigm(zi0 + bi);
        const float fg = sigm(zf0 + bf);
        const float gg = tanh_fast(zg0 + bg);
        const float og = sigm(zo0 + bo);
        const float cn = fg * creg[nb] + ig * gg;
        creg[nb] = cn;
        outh[(size_t)row * HH + n] = __float2half_rn(og * tanh_fast(cn));
    }
}

// ---------------- persistent fused LSTM ----------------
// Phase p: layer0 t=p (p<TT) + layer1 t=p-1 (p>0) in ONE merged GEMM pass.
// h(t) in buf[(t+1)&1]; h(-1)=zeros in buf[0]. Cell state lives in registers.
__global__ __launch_bounds__(512, 1) void lstm_persistent()
{
    extern __shared__ __align__(128) char smc[];
    const int tid = threadIdx.x;
    const int lane = tid & 31;
    const int w = tid >> 5;      // 0..15
    const int wm = w & 3;        // m-frag row block
    const int wn = w >> 2;       // n quarter (8 hidden cols)
    const int mwb = wm * 16;
    const int b = blockIdx.x;
    const int m0 = (b & 15) * 64;
    const int s = b >> 4;        // slice 0..7 (32 hidden cols)
    const int grp = b & 15;
    const int lrow = tid >> 3;   // A-loader row 0..63
    const int lq = tid & 7;      // A-loader 8B unit
    const int mg = m0 + lrow;

    // ---- prologue: W slice + biases into SMEM ----
    {
        const uint4* w0s = (const uint4*)((const char*)g_Wp0 + (size_t)s * 81920);
        uint4* w0d = (uint4*)(smc + SM_W0);
        for (int i = tid; i < 81920 / 16; i += 512) w0d[i] = w0s[i];
        const uint4* w1s = (const uint4*)((const char*)g_Wp1 + (size_t)s * 131072);
        uint4* w1d = (uint4*)(smc + SM_W1);
        for (int i = tid; i < 131072 / 16; i += 512) w1d[i] = w1s[i];
        float* b0d = (float*)(smc + SM_B0);
        float* b1d = (float*)(smc + SM_B1);
        for (int i = tid; i < G4; i += 512) { b0d[i] = g_b0[i]; b1d[i] = g_b1[i]; }
    }
    __syncthreads();

    float c0reg[4] = {0.f, 0.f, 0.f, 0.f};
    float c1reg[4] = {0.f, 0.f, 0.f, 0.f};

    for (int p = 0; p <= TT; ++p) {
        const bool do0 = (p < TT);
        const bool do1 = (p > 0);
        const int cstart = do0 ? 0 : 2;
        const int cend = do1 ? 18 : 10;

        float acc0[4][4], acc1[4][4];
#pragma unroll
        for (int nb = 0; nb < 4; ++nb)
#pragma unroll
            for (int j = 0; j < 4; ++j) { acc0[nb][j] = 0.f; acc1[nb][j] = 0.f; }

        uint2 ph = load_chunk(cstart, p, mg, lq);
        *(uint2*)(smc + SM_A + (cstart & 1) * 5120 + lrow * 80 + lq * 8) = ph;
        if (cstart + 1 < cend) ph = load_chunk(cstart + 1, p, mg, lq);
        __syncthreads();

        for (int c = cstart; c < cend; ++c) {
            if (c + 1 < cend)
                *(uint2*)(smc + SM_A + ((c + 1) & 1) * 5120 + lrow * 80 + lq * 8) = ph;
            if (c + 2 < cend) ph = load_chunk(c + 2, p, mg, lq);

            const char* sAc = smc + SM_A + (c & 1) * 5120;
#pragma unroll
            for (int ks = 0; ks < 2; ++ks) {
                const int abase = (mwb + (lane >> 2)) * 80 + (lane & 3) * 4 + ks * 32;
                const uint32_t a0r = *(const uint32_t*)(sAc + abase);
                const uint32_t a1r = *(const uint32_t*)(sAc + abase + 8 * 80);
                const uint32_t a2r = *(const uint32_t*)(sAc + abase + 16);
                const uint32_t a3r = *(const uint32_t*)(sAc + abase + 8 * 80 + 16);

                if (do0 && c < 10) {
                    const char* bp = smc + SM_W0 + (size_t)(c * 2 + ks) * 4096
                                   + wn * 1024 + lane * 16;
                    const uint4 w0 = *(const uint4*)bp;
                    const uint4 w1 = *(const uint4*)(bp + 512);
                    mma16816(acc0[0], a0r, a1r, a2r, a3r, w0.x, w0.y);
                    mma16816(acc0[1], a0r, a1r, a2r, a3r, w0.z, w0.w);
                    mma16816(acc0[2], a0r, a1r, a2r, a3r, w1.x, w1.y);
                    mma16816(acc0[3], a0r, a1r, a2r, a3r, w1.z, w1.w);
                }
                if (do1 && c >= 2) {
                    const char* bp = smc + SM_W1 + (size_t)((c - 2) * 2 + ks) * 4096
                                   + wn * 1024 + lane * 16;
                    const uint4 w0 = *(const uint4*)bp;
                    const uint4 w1 = *(const uint4*)(bp + 512);
                    mma16816(acc1[0], a0r, a1r, a2r, a3r, w0.x, w0.y);
                    mma16816(acc1[1], a0r, a1r, a2r, a3r, w0.z, w0.w);
                    mma16816(acc1[2], a0r, a1r, a2r, a3r, w1.x, w1.y);
                    mma16816(acc1[3], a0r, a1r, a2r, a3r, w1.z, w1.w);
                }
            }
            __syncthreads();
        }

        if (do0)
            cell_epilogue(acc0, c0reg, smc + SM_B0, g_h0[(p + 1) & 1], m0, s, mwb, wn, lane);
        if (do1)
            cell_epilogue(acc1, c1reg, smc + SM_B1, g_h1[p & 1], m0, s, mwb, wn, lane);

        group_sync(grp);
    }
}

// ---------------- final FC (O=1) ----------------
__global__ void fc_kernel(const float* __restrict__ fc_w, const float* __restrict__ fc_b,
                          float* __restrict__ out)
{
    const __half* h = g_h1[TT & 1];
    const int warp = (blockIdx.x * blockDim.x + threadIdx.x) >> 5;
    const int lane = threadIdx.x & 31;
    if (warp >= BB) return;
    float sum = 0.f;
    for (int k = lane; k < HH; k += 32)
        sum += __half2float(h[warp * HH + k]) * fc_w[k];
#pragma unroll
    for (int off = 16; off; off >>= 1) sum += __shfl_xor_sync(0xffffffffu, sum, off);
    if (lane == 0) out[warp] = sum + fc_b[0];
}

// ---------------- launch ----------------
extern "C" void kernel_launch(void* const* d_in, const int* in_sizes, int n_in,
                              void* d_out, int out_size)
{
    const float* x     = (const float*)d_in[0];
    const float* w_ih0 = (const float*)d_in[1];
    const float* w_hh0 = (const float*)d_in[2];
    const float* b_ih0 = (const float*)d_in[3];
    const float* b_hh0 = (const float*)d_in[4];
    const float* w_ih1 = (const float*)d_in[5];
    const float* w_hh1 = (const float*)d_in[6];
    const float* b_ih1 = (const float*)d_in[7];
    const float* b_hh1 = (const float*)d_in[8];
    const float* fc_w  = (const float*)d_in[9];
    const float* fc_b  = (const float*)d_in[10];
    float* out = (float*)d_out;

    cudaFuncSetAttribute(lstm_persistent,
                         cudaFuncAttributeMaxDynamicSharedMemorySize, SMEM_TOTAL);

    pack_init<<<2048, 256>>>(x, w_ih0, w_hh0, b_ih0, b_hh0,
                             w_ih1, w_hh1, b_ih1, b_hh1);
    lstm_persistent<<<NBLK, 512, SMEM_TOTAL>>>();
    fc_kernel<<<BB * 32 / 256, 256>>>(fc_w, fc_b, out);
}

// round 11
// speedup vs baseline: 6.7088x; 1.1735x over previous
#include <cuda_runtime.h>
#include <cuda_fp16.h>
#include <cstddef>
#include <cstdint>

#define BB 1024   // batch
#define TT 512    // time steps
#define II 64     // input dim
#define HH 256    // hidden dim
#define G4 1024   // 4*H
#define NBLK 128  // 16 m-tiles x 8 slices
#define KC0 (II + HH)    // 320
#define KC1 (HH + HH)    // 512
#define KB0 (KC0 / 16)   // 20
#define KB1 (KC1 / 16)   // 32

// ---- smem layout (bytes) ----
#define SM_W0 0               // 65536  : W0 chunks 2-9 (h-part) fragments
#define SM_W1 65536           // 131072 : W1 fragments (chunks 2-17 -> 0-15)
#define SM_A  196608          // 4 x 5120 : A chunk buffers (64 rows x 80B)
#define SM_B0 217088          // 4096 : bias0
#define SM_B1 221184          // 4096 : bias1
#define SMEM_TOTAL 225280

// ---------------- persistent device scratch ----------------
// Prepacked W fragments, fp16. Per (slice, kblk): 4 warp-n quarters x 2 pairs
// x 32 lanes x 16B; a lane's 16B = B-fragments for 2 adjacent n-frags.
__device__ __align__(16) __half g_Wp0[8 * 128 * KC0];
__device__ __align__(16) __half g_Wp1[8 * 128 * KC1];
__device__ float g_b0[G4];
__device__ float g_b1[G4];
__device__ __align__(16) __half g_xh[(size_t)TT * BB * II];  // [t][b][k]
__device__ __align__(16) __half g_h0[2][BB * HH];
__device__ __align__(16) __half g_h1[2][BB * HH];
// per-m-group barriers (16 groups of 8 CTAs), padded lines
__device__ unsigned g_bar_count[16 * 32];
__device__ unsigned g_bar_gen[16 * 32];

// ---------------- helpers ----------------
__device__ __forceinline__ uint32_t smem_u32(const void* p) {
    uint32_t a;
    asm("{ .reg .u64 t; cvta.to.shared.u64 t, %1; cvt.u32.u64 %0, t; }" : "=r"(a) : "l"(p));
    return a;
}

// ---------------- weight fragment packing ----------------
__device__ void packW(__half* __restrict__ Wp,
                      const float* __restrict__ wih, const float* __restrict__ whh,
                      int KIN, int KC, int KCb, int tid, int stride)
{
    const int nunits = 8 * KCb * 4 * 2 * 32;   // slices x kblks x wn x pair x lane
    for (int idx = tid; idx < nunits; idx += stride) {
        const int u = idx & 31;
        const int j = (idx >> 5) & 1;
        const int wn = (idx >> 6) & 3;
        int rest = idx >> 8;
        const int kb = rest % KCb;
        const int s = rest / KCb;
        const int col = u >> 2, kp = u & 3;
        const size_t base = (size_t)s * KC * 128 + (size_t)kb * 2048
                          + (wn * 2 + j) * 256 + u * 8;
        const int kbase = kb * 16 + 2 * kp;
        const int kks[4] = { kbase, kbase + 1, kbase + 8, kbase + 9 };
#pragma unroll
        for (int f = 0; f < 2; ++f) {
            const int nfrag = wn * 4 + j * 2 + f;
            const int np = nfrag * 8 + col;
            const int gate = np & 3, nh = np >> 2;
            const int row = gate * HH + s * 32 + nh;
#pragma unroll
            for (int jj = 0; jj < 4; ++jj) {
                const int kk = kks[jj];
                const float wv = (kk < KIN) ? wih[row * KIN + kk]
                                            : whh[row * HH + (kk - KIN)];
                Wp[base + f * 4 + jj] = __float2half_rn(wv);
            }
        }
    }
}

__global__ void pack_init(const float* __restrict__ x,
                          const float* __restrict__ w_ih0, const float* __restrict__ w_hh0,
                          const float* __restrict__ b_ih0, const float* __restrict__ b_hh0,
                          const float* __restrict__ w_ih1, const float* __restrict__ w_hh1,
                          const float* __restrict__ b_ih1, const float* __restrict__ b_hh1)
{
    const int tid = blockIdx.x * blockDim.x + threadIdx.x;
    const int stride = gridDim.x * blockDim.x;

    packW(g_Wp0, w_ih0, w_hh0, II, KC0, KB0, tid, stride);
    packW(g_Wp1, w_ih1, w_hh1, HH, KC1, KB1, tid, stride);

    for (int idx = tid; idx < G4; idx += stride) {
        g_b0[idx] = b_ih0[idx] + b_hh0[idx];
        g_b1[idx] = b_ih1[idx] + b_hh1[idx];
    }
    for (size_t idx = tid; idx < (size_t)TT * BB * II; idx += stride) {
        const int k = idx % II;
        const int b = (idx / II) % BB;
        const int t = idx / ((size_t)II * BB);
        g_xh[idx] = __float2half_rn(x[((size_t)b * TT + t) * II + k]);
    }
    const __half z = __float2half_rn(0.f);
    for (int idx = tid; idx < BB * HH; idx += stride) {
        g_h0[0][idx] = z;
        g_h1[0][idx] = z;
    }
    for (int idx = tid; idx < 16 * 32; idx += stride) {
        g_bar_count[idx] = 0;
        g_bar_gen[idx] = 0;
    }
}

// ---------------- per-m-group barrier (8 CTAs) ----------------
__device__ __forceinline__ void group_sync(int grp)
{
    __threadfence();
    __syncthreads();
    if (threadIdx.x == 0) {
        volatile unsigned* genp = &g_bar_gen[grp * 32];
        const unsigned gen = *genp;
        if (atomicAdd(&g_bar_count[grp * 32], 1u) == 7u) {
            *(volatile unsigned*)&g_bar_count[grp * 32] = 0u;
            __threadfence();
            *genp = gen + 1u;
        } else {
            while (*genp == gen) {}
        }
    }
    __syncthreads();
}

// ---------------- mma wrapper ----------------
__device__ __forceinline__ void mma16816(float* d,
                                         uint32_t a0, uint32_t a1, uint32_t a2, uint32_t a3,
                                         uint32_t b0, uint32_t b1)
{
    asm volatile("mma.sync.aligned.m16n8k16.row.col.f32.f16.f16.f32 "
                 "{%0,%1,%2,%3}, {%4,%5,%6,%7}, {%8,%9}, {%0,%1,%2,%3};\n"
                 : "+f"(d[0]), "+f"(d[1]), "+f"(d[2]), "+f"(d[3])
                 : "r"(a0), "r"(a1), "r"(a2), "r"(a3), "r"(b0), "r"(b1));
}

__device__ __forceinline__ float sigm(float z) { return 1.f / (1.f + __expf(-z)); }
__device__ __forceinline__ float tanh_fast(float z) { return 2.f / (1.f + __expf(-2.f * z)) - 1.f; }

// chunk source: c 0-1 -> x(p); c 2-9 -> h0(p-1); c 10-17 -> h1(p-2)
__device__ __forceinline__ uint2 load_chunk(int c, int p, int mg, int lq)
{
    const __half* src;
    int str, koff;
    if (c < 2)       { src = g_xh + (size_t)p * BB * II; str = II; koff = c * 32; }
    else if (c < 10) { src = g_h0[p & 1];        str = HH; koff = (c - 2) * 32; }
    else             { src = g_h1[(p - 1) & 1];  str = HH; koff = (c - 10) * 32; }
    return *(const uint2*)(src + (size_t)mg * str + koff + lq * 4);
}

// ---------------- one chunk of fused GEMM ----------------
// aAddr: u32 smem addr (per-lane ldmatrix base incl. buffer offset).
// w0p/w1p: per-(wn,lane) fragment base for this chunk (smem or global).
__device__ __forceinline__ void compute_chunk(
    uint32_t aAddr, const char* w0p, const char* w1p,
    float (*acc0)[4], float (*acc1)[4], bool l0, bool l1)
{
#pragma unroll
    for (int ks = 0; ks < 2; ++ks) {
        uint32_t a0r, a1r, a2r, a3r;
        asm volatile("ldmatrix.sync.aligned.m8n8.x4.shared.b16 {%0,%1,%2,%3}, [%4];"
                     : "=r"(a0r), "=r"(a1r), "=r"(a2r), "=r"(a3r)
                     : "r"(aAddr + ks * 32));
        if (l0) {
            const uint4 w0 = *(const uint4*)(w0p + ks * 4096);
            const uint4 w1 = *(const uint4*)(w0p + ks * 4096 + 512);
            mma16816(acc0[0], a0r, a1r, a2r, a3r, w0.x, w0.y);
            mma16816(acc0[1], a0r, a1r, a2r, a3r, w0.z, w0.w);
            mma16816(acc0[2], a0r, a1r, a2r, a3r, w1.x, w1.y);
            mma16816(acc0[3], a0r, a1r, a2r, a3r, w1.z, w1.w);
        }
        if (l1) {
            const uint4 w0 = *(const uint4*)(w1p + ks * 4096);
            const uint4 w1 = *(const uint4*)(w1p + ks * 4096 + 512);
            mma16816(acc1[0], a0r, a1r, a2r, a3r, w0.x, w0.y);
            mma16816(acc1[1], a0r, a1r, a2r, a3r, w0.z, w0.w);
            mma16816(acc1[2], a0r, a1r, a2r, a3r, w1.x, w1.y);
            mma16816(acc1[3], a0r, a1r, a2r, a3r, w1.z, w1.w);
        }
    }
}

// ---------------- cell epilogue: c in registers ----------------
__device__ __forceinline__ void cell_epilogue(
    float (*acc)[4], float* __restrict__ creg, const char* smem_bias,
    __half* __restrict__ outh, int m0, int s, int mwb, int wn, int lane)
{
    const int par = lane & 1;
    const int row = m0 + mwb + (lane >> 2) + par * 8;
    const int nbase = s * 32 + wn * 8 + ((lane & 2) >> 1);
#pragma unroll
    for (int nb = 0; nb < 4; ++nb) {
        const float f0 = acc[nb][0], f1 = acc[nb][1], f2 = acc[nb][2], f3 = acc[nb][3];
        const float p0 = __shfl_xor_sync(0xffffffffu, f0, 1);
        const float p1 = __shfl_xor_sync(0xffffffffu, f1, 1);
        const float p2 = __shfl_xor_sync(0xffffffffu, f2, 1);
        const float p3 = __shfl_xor_sync(0xffffffffu, f3, 1);
        const float zi0 = par ? p2 : f0;
        const float zf0 = par ? p3 : f1;
        const float zg0 = par ? f2 : p0;
        const float zo0 = par ? f3 : p1;
        const int n = nbase + nb * 2;
        const float bi = *(const float*)(smem_bias + n * 4);
        const float bf = *(const float*)(smem_bias + (HH + n) * 4);
        const float bg = *(const float*)(smem_bias + (2 * HH + n) * 4);
        const float bo = *(const float*)(smem_bias + (3 * HH + n) * 4);
        const float ig = sigm(zi0 + bi);
        const float fg = sigm(zf0 + bf);
        const float gg = tanh_fast(zg0 + bg);
        const float og = sigm(zo0 + bo);
        const float cn = fg * creg[nb] + ig * gg;
        creg[nb] = cn;
        outh[(size_t)row * HH + n] = __float2half_rn(og * tanh_fast(cn));
    }
}

// ---------------- persistent fused LSTM ----------------
// Phase p: layer0 t=p (p<TT) + layer1 t=p-1 (p>0) in one merged GEMM pass.
// h(t) in buf[(t+1)&1]; h(-1)=zeros in buf[0]. Cell state in registers.
__global__ __launch_bounds__(512, 1) void lstm_persistent()
{
    extern __shared__ __align__(128) char smc[];
    const int tid = threadIdx.x;
    const int lane = tid & 31;
    const int w = tid >> 5;      // 0..15
    const int wm = w & 3;
    const int wn = w >> 2;       // 8 hidden cols quarter
    const int mwb = wm * 16;
    const int b = blockIdx.x;
    const int m0 = (b & 15) * 64;
    const int s = b >> 4;        // slice 0..7
    const int grp = b & 15;
    const int lrow = tid >> 3;   // A-loader row 0..63
    const int lq = tid & 7;      // A-loader 8B unit
    const int mg = m0 + lrow;

    // ---- prologue: W slice (h-part of W0, all of W1) + biases to SMEM ----
    {
        const uint4* w0s = (const uint4*)((const char*)g_Wp0 + (size_t)s * 81920 + 16384);
        uint4* w0d = (uint4*)(smc + SM_W0);
        for (int i = tid; i < 65536 / 16; i += 512) w0d[i] = w0s[i];
        const uint4* w1s = (const uint4*)((const char*)g_Wp1 + (size_t)s * 131072);
        uint4* w1d = (uint4*)(smc + SM_W1);
        for (int i = tid; i < 131072 / 16; i += 512) w1d[i] = w1s[i];
        float* b0d = (float*)(smc + SM_B0);
        float* b1d = (float*)(smc + SM_B1);
        for (int i = tid; i < G4; i += 512) { b0d[i] = g_b0[i]; b1d[i] = g_b1[i]; }
    }
    __syncthreads();

    // ldmatrix per-lane base address (buffer 0, ks 0)
    const uint32_t aU = smem_u32(smc) + SM_A + (mwb + (lane & 15)) * 80 + ((lane >> 4) << 4);
    const char* w0gbase = (const char*)g_Wp0 + (size_t)s * 81920 + wn * 1024 + lane * 16;
    const char* w0sbase = smc + SM_W0 + wn * 1024 + lane * 16;
    const char* w1sbase = smc + SM_W1 + wn * 1024 + lane * 16;

    float c0reg[4] = {0.f, 0.f, 0.f, 0.f};
    float c1reg[4] = {0.f, 0.f, 0.f, 0.f};

    for (int p = 0; p <= TT; ++p) {
        const bool do0 = (p < TT);
        const bool do1 = (p > 0);

        float acc0[4][4], acc1[4][4];
#pragma unroll
        for (int nb = 0; nb < 4; ++nb)
#pragma unroll
            for (int j = 0; j < 4; ++j) { acc0[nb][j] = 0.f; acc1[nb][j] = 0.f; }

        if (do0 && do1) {
            // ---- steady state: 18 chunks as 9 pairs, 1 sync per pair ----
            uint2 ph0 = load_chunk(0, p, mg, lq);
            uint2 ph1 = load_chunk(1, p, mg, lq);
#pragma unroll
            for (int j = 0; j < 9; ++j) {
                const int set = (j & 1) << 1;
                *(uint2*)(smc + SM_A + set * 5120 + lrow * 80 + lq * 8) = ph0;
                *(uint2*)(smc + SM_A + (set + 1) * 5120 + lrow * 80 + lq * 8) = ph1;
                if (j < 8) {
                    ph0 = load_chunk(2 * j + 2, p, mg, lq);
                    ph1 = load_chunk(2 * j + 3, p, mg, lq);
                }
                __syncthreads();
#pragma unroll
                for (int q = 0; q < 2; ++q) {
                    const int c = 2 * j + q;
                    const char* w0p = (c < 2) ? (w0gbase + c * 8192)
                                              : (w0sbase + (c - 2) * 8192);
                    const char* w1p = w1sbase + (c >= 2 ? (c - 2) * 8192 : 0);
                    compute_chunk(aU + (set + q) * 5120, w0p, w1p,
                                  acc0, acc1, c < 10, c >= 2);
                }
            }
        } else {
            // ---- boundary phases (p==0 or p==TT): generic 2-buffer path ----
            const int cstart = do0 ? 0 : 2;
            const int cend = do1 ? 18 : 10;
            uint2 ph = load_chunk(cstart, p, mg, lq);
            *(uint2*)(smc + SM_A + (cstart & 1) * 5120 + lrow * 80 + lq * 8) = ph;
            if (cstart + 1 < cend) ph = load_chunk(cstart + 1, p, mg, lq);
            __syncthreads();
            for (int c = cstart; c < cend; ++c) {
                if (c + 1 < cend)
                    *(uint2*)(smc + SM_A + ((c + 1) & 1) * 5120 + lrow * 80 + lq * 8) = ph;
                if (c + 2 < cend) ph = load_chunk(c + 2, p, mg, lq);
                const char* w0p = (c < 2) ? (w0gbase + c * 8192)
                                          : (w0sbase + (c - 2) * 8192);
                const char* w1p = w1sbase + (c >= 2 ? (c - 2) * 8192 : 0);
                compute_chunk(aU + (c & 1) * 5120, w0p, w1p,
                              acc0, acc1, do0 && c < 10, do1 && c >= 2);
                __syncthreads();
            }
        }

        if (do0)
            cell_epilogue(acc0, c0reg, smc + SM_B0, g_h0[(p + 1) & 1], m0, s, mwb, wn, lane);
        if (do1)
            cell_epilogue(acc1, c1reg, smc + SM_B1, g_h1[p & 1], m0, s, mwb, wn, lane);

        group_sync(grp);
    }
}

// ---------------- final FC (O=1) ----------------
__global__ void fc_kernel(const float* __restrict__ fc_w, const float* __restrict__ fc_b,
                          float* __restrict__ out)
{
    const __half* h = g_h1[TT & 1];
    const int warp = (blockIdx.x * blockDim.x + threadIdx.x) >> 5;
    const int lane = threadIdx.x & 31;
    if (warp >= BB) return;
    float sum = 0.f;
    for (int k = lane; k < HH; k += 32)
        sum += __half2float(h[warp * HH + k]) * fc_w[k];
#pragma unroll
    for (int off = 16; off; off >>= 1) sum += __shfl_xor_sync(0xffffffffu, sum, off);
    if (lane == 0) out[warp] = sum + fc_b[0];
}

// ---------------- launch ----------------
extern "C" void kernel_launch(void* const* d_in, const int* in_sizes, int n_in,
                              void* d_out, int out_size)
{
    const float* x     = (const float*)d_in[0];
    const float* w_ih0 = (const float*)d_in[1];
    const float* w_hh0 = (const float*)d_in[2];
    const float* b_ih0 = (const float*)d_in[3];
    const float* b_hh0 = (const float*)d_in[4];
    const float* w_ih1 = (const float*)d_in[5];
    const float* w_hh1 = (const float*)d_in[6];
    const float* b_ih1 = (const float*)d_in[7];
    const float* b_hh1 = (const float*)d_in[8];
    const float* fc_w  = (const float*)d_in[9];
    const float* fc_b  = (const float*)d_in[10];
    float* out = (float*)d_out;

    cudaFuncSetAttribute(lstm_persistent,
                         cudaFuncAttributeMaxDynamicSharedMemorySize, SMEM_TOTAL);

    pack_init<<<2048, 256>>>(x, w_ih0, w_hh0, b_ih0, b_hh0,
                             w_ih1, w_hh1, b_ih1, b_hh1);
    lstm_persistent<<<NBLK, 512, SMEM_TOTAL>>>();
    fc_kernel<<<BB * 32 / 256, 256>>>(fc_w, fc_b, out);
}